// round 5
// baseline (speedup 1.0000x reference)
#include <cuda_runtime.h>
#include <cuda_bf16.h>
#include <math.h>

#define N_NODES 50000
#define NODE_DIM 64
#define DEPTH 2
#define FEAT 192           // 64*(DEPTH+1)
#define E_EDGES 1200000
#define R_REL 500
#define DEG 24

// ---------------- scratch (device globals: allocation-free) ----------------
__device__ float    g_nrel[R_REL * NODE_DIM];   // l2-normalized rel_emb
__device__ float    g_attW[DEPTH * R_REL];      // per-relation attention logit per layer
__device__ unsigned g_npT[FEAT * 64];           // normalized proxy, transposed [k][n], tf32 bits
__device__ unsigned g_Wt[FEAT * FEAT];          // gate_w transposed [k][c], tf32 bits
__device__ unsigned g_prx[64 * FEAT];           // proxy [k][n], tf32 bits

__device__ __forceinline__ unsigned f2tf(float x) {
    unsigned r;
    asm("cvt.rna.tf32.f32 %0, %1;" : "=r"(r) : "f"(x));
    return r;
}

// ---------------- prep: normalize rel table + proxy(->transposed tf32) -----
__global__ void prep_kernel(const float* __restrict__ rel_emb,
                            const float* __restrict__ attn_kernels,
                            const float* __restrict__ proxy) {
    int w = (blockIdx.x * blockDim.x + threadIdx.x) >> 5;
    int lane = threadIdx.x & 31;
    if (w < R_REL) {
        float2 v = ((const float2*)(rel_emb + w * NODE_DIM))[lane];
        float ss = v.x * v.x + v.y * v.y;
        #pragma unroll
        for (int o = 16; o; o >>= 1) ss += __shfl_xor_sync(0xffffffffu, ss, o);
        float inv = 1.0f / fmaxf(sqrtf(ss), 1e-12f);
        float2 nv = make_float2(v.x * inv, v.y * inv);
        ((float2*)(g_nrel + w * NODE_DIM))[lane] = nv;
        float2 a0 = ((const float2*)attn_kernels)[lane];
        float2 a1 = ((const float2*)(attn_kernels + NODE_DIM))[lane];
        float d0 = nv.x * a0.x + nv.y * a0.y;
        float d1 = nv.x * a1.x + nv.y * a1.y;
        #pragma unroll
        for (int o = 16; o; o >>= 1) {
            d0 += __shfl_xor_sync(0xffffffffu, d0, o);
            d1 += __shfl_xor_sync(0xffffffffu, d1, o);
        }
        if (lane == 0) { g_attW[w] = d0; g_attW[R_REL + w] = d1; }
    } else if (w < R_REL + 64) {
        int j = w - R_REL;
        float v[6];
        float ss = 0.f;
        #pragma unroll
        for (int t = 0; t < 6; t++) {
            v[t] = proxy[j * FEAT + lane + 32 * t];
            ss += v[t] * v[t];
        }
        #pragma unroll
        for (int o = 16; o; o >>= 1) ss += __shfl_xor_sync(0xffffffffu, ss, o);
        float inv = 1.0f / fmaxf(sqrtf(ss), 1e-12f);
        #pragma unroll
        for (int t = 0; t < 6; t++)
            g_npT[(lane + 32 * t) * 64 + j] = f2tf(v[t] * inv);   // transposed tf32
    }
}

// ---------------- convert gate_w (transposed) + proxy to tf32 tables --------
__global__ void convtab_kernel(const float* __restrict__ gw,
                               const float* __restrict__ proxy) {
    int idx = blockIdx.x * blockDim.x + threadIdx.x;
    if (idx < FEAT * FEAT) {
        int k = idx / FEAT, c = idx - k * FEAT;
        g_Wt[idx] = f2tf(gw[c * FEAT + k]);
    } else if (idx < FEAT * FEAT + 64 * FEAT) {
        int j = idx - FEAT * FEAT;
        g_prx[j] = f2tf(proxy[j]);
    }
}

// ---------------- layer 0 input: outputs[:,0:64] = tanh(features) ----------
__global__ void tanh_kernel(const float* __restrict__ features, float* __restrict__ out) {
    int idx = blockIdx.x * blockDim.x + threadIdx.x;
    if (idx >= N_NODES * NODE_DIM) return;
    int i = idx >> 6;
    int j = idx & 63;
    out[i * FEAT + j] = tanhf(features[idx]);
}

// ---------------- graph attention layer: smem feature window ---------------
// Block = 256 threads (8 warps), 64 nodes/block, each warp owns 8 nodes.
// Neighbors are gathered from a 227-row smem window when in range (banded
// adjacency fast path) with a global-load fallback for out-of-window edges.
#define NB 64
#define WIN (NB + 163)     // 227 rows covers src in [n0+1, n0+63+162]
__global__ void __launch_bounds__(256, 3) layer_kernel(
        float* __restrict__ out,
        const int* __restrict__ src,
        const int* __restrict__ rid,
        const float* __restrict__ rval,
        int l) {
    extern __shared__ float sm[];
    float* s_f = sm;                      // WIN x 64 feature window
    int*   s_m = (int*)(s_f + WIN * 64);  // 64 nodes x 24: src | (rid<<16)
    float* s_w = (float*)(s_m + NB * DEG);// 64 nodes x 24: softmax weight

    int tid = threadIdx.x;
    int wb = tid >> 5;
    int lane = tid & 31;
    int n0 = blockIdx.x * NB;
    const float* fsrc = out + NODE_DIM * l;

    // ---- phase 1: load feature window rows [n0, n0+WIN) ----
    for (int i = tid; i < WIN * 16; i += 256) {
        int rr = i >> 4;
        int row = n0 + rr;
        int c4 = (i & 15) << 2;
        if (row < N_NODES)
            *(float4*)&s_f[rr * 64 + c4] = *(const float4*)(fsrc + (long)row * FEAT + c4);
    }

    // ---- phase 2: per-node metadata + segment softmax (warp: 8 nodes) ----
    #pragma unroll
    for (int nn = 0; nn < 8; nn++) {
        int node = n0 + wb * 8 + nn;
        if (node >= N_NODES) break;
        float att = -INFINITY;
        int ms = 0, mr = 0;
        if (lane < DEG) {
            int e = node * DEG + lane;
            ms = __ldg(src + e);
            mr = __ldg(rid + e);
            float sgn = __ldg(rval + e) < 0.f ? -1.f : 1.f;
            att = sgn * g_attW[l * R_REL + mr];
        }
        float m = att;
        #pragma unroll
        for (int o = 16; o; o >>= 1) m = fmaxf(m, __shfl_xor_sync(0xffffffffu, m, o));
        float ex = (lane < DEG) ? expf(att - m) : 0.f;
        float s = ex;
        #pragma unroll
        for (int o = 16; o; o >>= 1) s += __shfl_xor_sync(0xffffffffu, s, o);
        if (lane < DEG) {
            int idx = (wb * 8 + nn) * DEG + lane;
            s_m[idx] = ms | (mr << 16);
            s_w[idx] = ex / s;
        }
    }
    __syncthreads();

    // ---- phase 3: edge loops (half-warp per edge, float4 per lane) ----
    int half = lane >> 4;
    int q4 = (lane & 15) << 2;
    for (int nn = 0; nn < 8; nn++) {
        int node = n0 + wb * 8 + nn;
        if (node >= N_NODES) break;
        int mbase = (wb * 8 + nn) * DEG;
        float4 acc = make_float4(0.f, 0.f, 0.f, 0.f);
        #pragma unroll 4
        for (int i = 0; i < 12; i++) {
            int mi = mbase + 2 * i + half;
            int mm = s_m[mi];
            float we = s_w[mi];
            int srow = mm & 0xFFFF;
            int rrow = (mm >> 16) << 6;          // rid * 64
            int loc = srow - n0;
            float4 f;
            if ((unsigned)loc < (unsigned)WIN)
                f = *(const float4*)&s_f[loc * 64 + q4];
            else
                f = *(const float4*)(fsrc + (long)srow * FEAT + q4);
            float4 r = *(const float4*)(g_nrel + rrow + q4);
            float d = f.x * r.x + f.y * r.y + f.z * r.z + f.w * r.w;
            #pragma unroll
            for (int o = 8; o; o >>= 1) d += __shfl_xor_sync(0xffffffffu, d, o);
            float t2 = 2.f * d;
            acc.x += we * (f.x - t2 * r.x);
            acc.y += we * (f.y - t2 * r.y);
            acc.z += we * (f.z - t2 * r.z);
            acc.w += we * (f.w - t2 * r.w);
        }
        acc.x += __shfl_xor_sync(0xffffffffu, acc.x, 16);
        acc.y += __shfl_xor_sync(0xffffffffu, acc.y, 16);
        acc.z += __shfl_xor_sync(0xffffffffu, acc.z, 16);
        acc.w += __shfl_xor_sync(0xffffffffu, acc.w, 16);
        if (half == 0) {
            float* dst = out + (long)node * FEAT + NODE_DIM * (l + 1);
            *(float4*)(dst + q4) = make_float4(tanhf(acc.x), tanhf(acc.y),
                                               tanhf(acc.z), tanhf(acc.w));
        }
    }
}

// ---------------- tf32 mma helper -------------------------------------------
__device__ __forceinline__ void mma8(float* d, const unsigned* a, const unsigned* b) {
    asm volatile(
        "mma.sync.aligned.m16n8k8.row.col.f32.tf32.tf32.f32 "
        "{%0,%1,%2,%3}, {%4,%5,%6,%7}, {%8,%9}, {%0,%1,%2,%3};\n"
        : "+f"(d[0]), "+f"(d[1]), "+f"(d[2]), "+f"(d[3])
        : "r"(a[0]), "r"(a[1]), "r"(a[2]), "r"(a[3]), "r"(b[0]), "r"(b[1]));
}

// ---------------- fused final stage (tensor-core tf32) ----------------------
#define NT 64
#define SX 196
#define SP 68
__global__ void __launch_bounds__(256, 3) final_kernel(
        float* __restrict__ out,
        const float* __restrict__ gate_b) {
    extern __shared__ float smem[];
    float* s_x   = smem;                    // 64*196  (o, later pf)
    float* s_p   = s_x + NT * SX;           // 64*68
    float* s_inv = s_p + NT * SP;           // 64

    int tid = threadIdx.x;
    int w = tid >> 5, lane = tid & 31;
    int g = lane >> 2, t = lane & 3;
    int n0 = blockIdx.x * NT;
    int rows = N_NODES - n0; if (rows > NT) rows = NT;

    for (int i = tid; i < NT * 48; i += 256) {
        int r = i / 48, c4 = (i - r * 48) * 4;
        float4 v = (r < rows) ? *(const float4*)(out + (long)(n0 + r) * FEAT + c4)
                              : make_float4(0.f, 0.f, 0.f, 0.f);
        *(float4*)&s_x[r * SX + c4] = v;
    }
    __syncthreads();

    for (int r = w * 8; r < w * 8 + 8; r++) {
        float ss = 0.f;
        #pragma unroll
        for (int tt = 0; tt < 6; tt++) {
            float v = s_x[r * SX + lane + 32 * tt];
            ss += v * v;
        }
        #pragma unroll
        for (int o = 16; o; o >>= 1) ss += __shfl_xor_sync(0xffffffffu, ss, o);
        if (lane == 0) s_inv[r] = 1.0f / fmaxf(sqrtf(ss), 1e-12f);
    }
    __syncthreads();

    // ---- GEMM1: logits[64x64] = o @ nproxy^T ----
    {
        float d1[4][4];
        #pragma unroll
        for (int mi = 0; mi < 4; mi++)
            #pragma unroll
            for (int q = 0; q < 4; q++) d1[mi][q] = 0.f;
        for (int k0 = 0; k0 < FEAT; k0 += 8) {
            unsigned b[2];
            b[0] = __ldg(&g_npT[(k0 + t) * 64 + 8 * w + g]);
            b[1] = __ldg(&g_npT[(k0 + t + 4) * 64 + 8 * w + g]);
            #pragma unroll
            for (int mi = 0; mi < 4; mi++) {
                int r0 = 16 * mi + g;
                unsigned a[4];
                a[0] = f2tf(s_x[r0 * SX + k0 + t]);
                a[1] = f2tf(s_x[(r0 + 8) * SX + k0 + t]);
                a[2] = f2tf(s_x[r0 * SX + k0 + t + 4]);
                a[3] = f2tf(s_x[(r0 + 8) * SX + k0 + t + 4]);
                mma8(d1[mi], a, b);
            }
        }
        #pragma unroll
        for (int mi = 0; mi < 4; mi++) {
            int r0 = 16 * mi + g;
            int c = 8 * w + 2 * t;
            float i0 = s_inv[r0], i1 = s_inv[r0 + 8];
            s_p[r0 * SP + c]       = d1[mi][0] * i0;
            s_p[r0 * SP + c + 1]   = d1[mi][1] * i0;
            s_p[(r0 + 8) * SP + c]     = d1[mi][2] * i1;
            s_p[(r0 + 8) * SP + c + 1] = d1[mi][3] * i1;
        }
    }
    __syncthreads();

    for (int r = w * 8; r < w * 8 + 8; r++) {
        float v0 = s_p[r * SP + lane];
        float v1 = s_p[r * SP + 32 + lane];
        float mx = fmaxf(v0, v1);
        #pragma unroll
        for (int o = 16; o; o >>= 1) mx = fmaxf(mx, __shfl_xor_sync(0xffffffffu, mx, o));
        float e0 = expf(v0 - mx), e1 = expf(v1 - mx);
        float sm = e0 + e1;
        #pragma unroll
        for (int o = 16; o; o >>= 1) sm += __shfl_xor_sync(0xffffffffu, sm, o);
        float invs = 1.0f / sm;
        s_p[r * SP + lane] = e0 * invs;
        s_p[r * SP + 32 + lane] = e1 * invs;
    }
    __syncthreads();

    // ---- GEMM2: pf = o - P @ proxy (in-place) ----
    {
        float d2[3][4][4];
        #pragma unroll
        for (int ni = 0; ni < 3; ni++)
            #pragma unroll
            for (int mi = 0; mi < 4; mi++)
                #pragma unroll
                for (int q = 0; q < 4; q++) d2[ni][mi][q] = 0.f;
        for (int k0 = 0; k0 < 64; k0 += 8) {
            unsigned a[4][4];
            #pragma unroll
            for (int mi = 0; mi < 4; mi++) {
                int r0 = 16 * mi + g;
                a[mi][0] = f2tf(s_p[r0 * SP + k0 + t]);
                a[mi][1] = f2tf(s_p[(r0 + 8) * SP + k0 + t]);
                a[mi][2] = f2tf(s_p[r0 * SP + k0 + t + 4]);
                a[mi][3] = f2tf(s_p[(r0 + 8) * SP + k0 + t + 4]);
            }
            #pragma unroll
            for (int ni = 0; ni < 3; ni++) {
                int cb = 24 * w + 8 * ni + g;
                unsigned b[2];
                b[0] = __ldg(&g_prx[(k0 + t) * FEAT + cb]);
                b[1] = __ldg(&g_prx[(k0 + t + 4) * FEAT + cb]);
                #pragma unroll
                for (int mi = 0; mi < 4; mi++) mma8(d2[ni][mi], a[mi], b);
            }
        }
        #pragma unroll
        for (int ni = 0; ni < 3; ni++) {
            int c = 24 * w + 8 * ni + 2 * t;
            #pragma unroll
            for (int mi = 0; mi < 4; mi++) {
                int r0 = 16 * mi + g;
                s_x[r0 * SX + c]       = s_x[r0 * SX + c]       - d2[ni][mi][0];
                s_x[r0 * SX + c + 1]   = s_x[r0 * SX + c + 1]   - d2[ni][mi][1];
                s_x[(r0 + 8) * SX + c]     = s_x[(r0 + 8) * SX + c]     - d2[ni][mi][2];
                s_x[(r0 + 8) * SX + c + 1] = s_x[(r0 + 8) * SX + c + 1] - d2[ni][mi][3];
            }
        }
    }
    __syncthreads();

    // ---- GEMM3: pf @ W^T + b -> sigmoid -> blend -> global ----
    {
        float d3[3][4][4];
        #pragma unroll
        for (int ni = 0; ni < 3; ni++)
            #pragma unroll
            for (int mi = 0; mi < 4; mi++)
                #pragma unroll
                for (int q = 0; q < 4; q++) d3[ni][mi][q] = 0.f;
        for (int k0 = 0; k0 < FEAT; k0 += 8) {
            unsigned a[4][4];
            #pragma unroll
            for (int mi = 0; mi < 4; mi++) {
                int r0 = 16 * mi + g;
                a[mi][0] = f2tf(s_x[r0 * SX + k0 + t]);
                a[mi][1] = f2tf(s_x[(r0 + 8) * SX + k0 + t]);
                a[mi][2] = f2tf(s_x[r0 * SX + k0 + t + 4]);
                a[mi][3] = f2tf(s_x[(r0 + 8) * SX + k0 + t + 4]);
            }
            #pragma unroll
            for (int ni = 0; ni < 3; ni++) {
                int cb = 24 * w + 8 * ni + g;
                unsigned b[2];
                b[0] = __ldg(&g_Wt[(k0 + t) * FEAT + cb]);
                b[1] = __ldg(&g_Wt[(k0 + t + 4) * FEAT + cb]);
                #pragma unroll
                for (int mi = 0; mi < 4; mi++) mma8(d3[ni][mi], a[mi], b);
            }
        }
        #pragma unroll
        for (int ni = 0; ni < 3; ni++) {
            int c = 24 * w + 8 * ni + 2 * t;
            float b0 = __ldg(gate_b + c), b1 = __ldg(gate_b + c + 1);
            #pragma unroll
            for (int mi = 0; mi < 4; mi++) {
                int r0 = 16 * mi + g;
                #pragma unroll
                for (int half = 0; half < 2; half++) {
                    int r = r0 + 8 * half;
                    if (r >= rows) continue;
                    float p0 = d3[ni][mi][2 * half]     + b0;
                    float p1 = d3[ni][mi][2 * half + 1] + b1;
                    float g0 = 1.0f / (1.0f + expf(-p0));
                    float g1 = 1.0f / (1.0f + expf(-p1));
                    float2 o2 = *(const float2*)(out + (long)(n0 + r) * FEAT + c);
                    float pf0 = s_x[r * SX + c];
                    float pf1 = s_x[r * SX + c + 1];
                    float2 res = make_float2(g0 * o2.x + (1.0f - g0) * pf0,
                                             g1 * o2.y + (1.0f - g1) * pf1);
                    *(float2*)(out + (long)(n0 + r) * FEAT + c) = res;
                }
            }
        }
    }
}

extern "C" void kernel_launch(void* const* d_in, const int* in_sizes, int n_in,
                              void* d_out, int out_size) {
    const float* features     = (const float*)d_in[0];   // [N,64]
    const float* rel_emb      = (const float*)d_in[1];   // [R,64]
    const float* proxy        = (const float*)d_in[2];   // [64,192]
    const float* gate_w       = (const float*)d_in[3];   // [192,192]
    const float* gate_b       = (const float*)d_in[4];   // [192]
    const float* attn_kernels = (const float*)d_in[5];   // [2,64]
    const int*   adj          = (const int*)d_in[6];     // [2,E]
    const int*   r_index      = (const int*)d_in[7];     // [2,E]
    const float* r_val        = (const float*)d_in[8];   // [E]
    float* out = (float*)d_out;                          // [N,192]

    const int* src = adj + E_EDGES;
    const int* rid = r_index + E_EDGES;

    prep_kernel<<<(564 * 32 + 255) / 256, 256>>>(rel_emb, attn_kernels, proxy);
    convtab_kernel<<<(FEAT * FEAT + 64 * FEAT + 255) / 256, 256>>>(gate_w, proxy);

    tanh_kernel<<<(N_NODES * NODE_DIM + 255) / 256, 256>>>(features, out);

    size_t lsmem = (size_t)(WIN * 64) * sizeof(float)
                 + (size_t)(NB * DEG) * (sizeof(int) + sizeof(float));
    cudaFuncSetAttribute(layer_kernel, cudaFuncAttributeMaxDynamicSharedMemorySize, (int)lsmem);
    int lgrid = (N_NODES + NB - 1) / NB;
    layer_kernel<<<lgrid, 256, lsmem>>>(out, src, rid, r_val, 0);
    layer_kernel<<<lgrid, 256, lsmem>>>(out, src, rid, r_val, 1);

    size_t smem = (size_t)(NT * SX + NT * SP + NT) * sizeof(float);
    cudaFuncSetAttribute(final_kernel, cudaFuncAttributeMaxDynamicSharedMemorySize, (int)smem);
    final_kernel<<<(N_NODES + NT - 1) / NT, 256, smem>>>(out, gate_b);
}

// round 6
// speedup vs baseline: 1.0878x; 1.0878x over previous
#include <cuda_runtime.h>
#include <cuda_bf16.h>
#include <math.h>

#define N_NODES 50000
#define NODE_DIM 64
#define DEPTH 2
#define FEAT 192           // 64*(DEPTH+1)
#define E_EDGES 1200000
#define R_REL 500
#define DEG 24

// ---------------- scratch (device globals: allocation-free) ----------------
__device__ float    g_nrel[R_REL * NODE_DIM];   // l2-normalized rel_emb
__device__ float    g_attW[DEPTH * R_REL];      // per-relation attention logit per layer
__device__ unsigned g_npT[FEAT * 64];           // normalized proxy, transposed [k][n], tf32 bits
__device__ unsigned g_Wt[FEAT * FEAT];          // gate_w transposed [k][c], tf32 bits
__device__ unsigned g_prx[64 * FEAT];           // proxy [k][n], tf32 bits

__device__ __forceinline__ unsigned f2tf(float x) {
    unsigned r;
    asm("cvt.rna.tf32.f32 %0, %1;" : "=r"(r) : "f"(x));
    return r;
}

// ---------------- prep: normalize rel table + proxy(->transposed tf32) -----
__global__ void prep_kernel(const float* __restrict__ rel_emb,
                            const float* __restrict__ attn_kernels,
                            const float* __restrict__ proxy) {
    int w = (blockIdx.x * blockDim.x + threadIdx.x) >> 5;
    int lane = threadIdx.x & 31;
    if (w < R_REL) {
        float2 v = ((const float2*)(rel_emb + w * NODE_DIM))[lane];
        float ss = v.x * v.x + v.y * v.y;
        #pragma unroll
        for (int o = 16; o; o >>= 1) ss += __shfl_xor_sync(0xffffffffu, ss, o);
        float inv = 1.0f / fmaxf(sqrtf(ss), 1e-12f);
        float2 nv = make_float2(v.x * inv, v.y * inv);
        ((float2*)(g_nrel + w * NODE_DIM))[lane] = nv;
        float2 a0 = ((const float2*)attn_kernels)[lane];
        float2 a1 = ((const float2*)(attn_kernels + NODE_DIM))[lane];
        float d0 = nv.x * a0.x + nv.y * a0.y;
        float d1 = nv.x * a1.x + nv.y * a1.y;
        #pragma unroll
        for (int o = 16; o; o >>= 1) {
            d0 += __shfl_xor_sync(0xffffffffu, d0, o);
            d1 += __shfl_xor_sync(0xffffffffu, d1, o);
        }
        if (lane == 0) { g_attW[w] = d0; g_attW[R_REL + w] = d1; }
    } else if (w < R_REL + 64) {
        int j = w - R_REL;
        float v[6];
        float ss = 0.f;
        #pragma unroll
        for (int t = 0; t < 6; t++) {
            v[t] = proxy[j * FEAT + lane + 32 * t];
            ss += v[t] * v[t];
        }
        #pragma unroll
        for (int o = 16; o; o >>= 1) ss += __shfl_xor_sync(0xffffffffu, ss, o);
        float inv = 1.0f / fmaxf(sqrtf(ss), 1e-12f);
        #pragma unroll
        for (int t = 0; t < 6; t++)
            g_npT[(lane + 32 * t) * 64 + j] = f2tf(v[t] * inv);   // transposed tf32
    }
}

// ---------------- convert gate_w (transposed) + proxy to tf32 tables --------
__global__ void convtab_kernel(const float* __restrict__ gw,
                               const float* __restrict__ proxy) {
    int idx = blockIdx.x * blockDim.x + threadIdx.x;
    if (idx < FEAT * FEAT) {
        int k = idx / FEAT, c = idx - k * FEAT;
        g_Wt[idx] = f2tf(gw[c * FEAT + k]);
    } else if (idx < FEAT * FEAT + 64 * FEAT) {
        int j = idx - FEAT * FEAT;
        g_prx[j] = f2tf(proxy[j]);
    }
}

// ---------------- layer 0 input: outputs[:,0:64] = tanh(features) ----------
__global__ void tanh_kernel(const float* __restrict__ features, float* __restrict__ out) {
    int idx = blockIdx.x * blockDim.x + threadIdx.x;
    if (idx >= N_NODES * 16) return;
    int i = idx >> 4;
    int j4 = (idx & 15) << 2;
    float4 v = *(const float4*)(features + i * NODE_DIM + j4);
    *(float4*)(out + (long)i * FEAT + j4) =
        make_float4(tanhf(v.x), tanhf(v.y), tanhf(v.z), tanhf(v.w));
}

// ---------------- graph attention layer: warp per node ---------------------
// Quarter-warp edges: 4 edges per iteration, 8 lanes x 8 dims per edge.
__global__ void __launch_bounds__(256) layer_kernel(
        float* __restrict__ out,
        const int* __restrict__ src,
        const int* __restrict__ rid,
        const float* __restrict__ rval,
        int l) {
    __shared__ int4 s_meta[8 * DEG];            // per-warp edge table
    int wb = threadIdx.x >> 5;
    int w = (blockIdx.x * blockDim.x + threadIdx.x) >> 5;
    int lane = threadIdx.x & 31;
    if (w >= N_NODES) return;
    int base = w * DEG;

    // ---- metadata + segment softmax (lanes 0..23 hold one edge each) ----
    float att = -INFINITY;
    int ms = 0, mr = 0;
    if (lane < DEG) {
        int e = base + lane;
        ms = __ldg(src + e);
        mr = __ldg(rid + e);
        float sgn = __ldg(rval + e) < 0.f ? -1.f : 1.f;
        att = sgn * g_attW[l * R_REL + mr];
    }
    float m = att;
    #pragma unroll
    for (int o = 16; o; o >>= 1) m = fmaxf(m, __shfl_xor_sync(0xffffffffu, m, o));
    float ex = (lane < DEG) ? expf(att - m) : 0.f;
    float s = ex;
    #pragma unroll
    for (int o = 16; o; o >>= 1) s += __shfl_xor_sync(0xffffffffu, s, o);
    float wgt = ex / s;

    if (lane < DEG)
        s_meta[wb * DEG + lane] = make_int4(ms * FEAT + NODE_DIM * l,
                                            mr * NODE_DIM,
                                            __float_as_int(wgt), 0);
    __syncwarp();

    // ---- edge loop: 6 iterations x 4 edges (8 lanes x 8 dims each) ----
    int grp = lane >> 3;          // edge within the quad
    int q = lane & 7;
    int o1 = q << 2;              // dims [4q, 4q+4)
    int o2 = 32 + (q << 2);       // dims [32+4q, 32+4q+4)
    float4 acc0 = make_float4(0.f, 0.f, 0.f, 0.f);
    float4 acc1 = make_float4(0.f, 0.f, 0.f, 0.f);
    #pragma unroll
    for (int i = 0; i < 6; i++) {
        int4 md = s_meta[wb * DEG + 4 * i + grp];
        const float* fp = out + md.x;
        const float* rp = g_nrel + md.y;
        float4 f0 = *(const float4*)(fp + o1);
        float4 f1 = *(const float4*)(fp + o2);
        float4 r0 = *(const float4*)(rp + o1);
        float4 r1 = *(const float4*)(rp + o2);
        float d = f0.x * r0.x + f0.y * r0.y + f0.z * r0.z + f0.w * r0.w
                + f1.x * r1.x + f1.y * r1.y + f1.z * r1.z + f1.w * r1.w;
        d += __shfl_xor_sync(0xffffffffu, d, 1);
        d += __shfl_xor_sync(0xffffffffu, d, 2);
        d += __shfl_xor_sync(0xffffffffu, d, 4);
        float we = __int_as_float(md.z);
        float t2 = 2.f * d;
        acc0.x += we * (f0.x - t2 * r0.x);
        acc0.y += we * (f0.y - t2 * r0.y);
        acc0.z += we * (f0.z - t2 * r0.z);
        acc0.w += we * (f0.w - t2 * r0.w);
        acc1.x += we * (f1.x - t2 * r1.x);
        acc1.y += we * (f1.y - t2 * r1.y);
        acc1.z += we * (f1.z - t2 * r1.z);
        acc1.w += we * (f1.w - t2 * r1.w);
    }
    // combine the 4 groups
    #pragma unroll
    for (int o = 8; o <= 16; o <<= 1) {
        acc0.x += __shfl_xor_sync(0xffffffffu, acc0.x, o);
        acc0.y += __shfl_xor_sync(0xffffffffu, acc0.y, o);
        acc0.z += __shfl_xor_sync(0xffffffffu, acc0.z, o);
        acc0.w += __shfl_xor_sync(0xffffffffu, acc0.w, o);
        acc1.x += __shfl_xor_sync(0xffffffffu, acc1.x, o);
        acc1.y += __shfl_xor_sync(0xffffffffu, acc1.y, o);
        acc1.z += __shfl_xor_sync(0xffffffffu, acc1.z, o);
        acc1.w += __shfl_xor_sync(0xffffffffu, acc1.w, o);
    }
    if (grp == 0) {
        float* dst = out + (long)w * FEAT + NODE_DIM * (l + 1);
        *(float4*)(dst + o1) = make_float4(tanhf(acc0.x), tanhf(acc0.y),
                                           tanhf(acc0.z), tanhf(acc0.w));
        *(float4*)(dst + o2) = make_float4(tanhf(acc1.x), tanhf(acc1.y),
                                           tanhf(acc1.z), tanhf(acc1.w));
    }
}

// ---------------- tf32 mma helper -------------------------------------------
__device__ __forceinline__ void mma8(float* d, const unsigned* a, const unsigned* b) {
    asm volatile(
        "mma.sync.aligned.m16n8k8.row.col.f32.tf32.tf32.f32 "
        "{%0,%1,%2,%3}, {%4,%5,%6,%7}, {%8,%9}, {%0,%1,%2,%3};\n"
        : "+f"(d[0]), "+f"(d[1]), "+f"(d[2]), "+f"(d[3])
        : "r"(a[0]), "r"(a[1]), "r"(a[2]), "r"(a[3]), "r"(b[0]), "r"(b[1]));
}

// ---------------- fused final stage (tensor-core tf32) ----------------------
// 512 threads (16 warps): warp = (mg, ng); mg splits the 64 rows in two
// 32-row halves (2 m16-tiles each), ng the n-dimension as before.
#define NT 64
#define SX 196
#define SP 68
__global__ void __launch_bounds__(512, 2) final_kernel(
        float* __restrict__ out,
        const float* __restrict__ gate_b) {
    extern __shared__ float smem[];
    float* s_x   = smem;                    // 64*196  (o, later pf)
    float* s_p   = s_x + NT * SX;           // 64*68
    float* s_inv = s_p + NT * SP;           // 64

    int tid = threadIdx.x;
    int w = tid >> 5, lane = tid & 31;
    int g = lane >> 2, t = lane & 3;
    int mg = w >> 3, ng = w & 7;
    int n0 = blockIdx.x * NT;
    int rows = N_NODES - n0; if (rows > NT) rows = NT;

    for (int i = tid; i < NT * 48; i += 512) {
        int r = i / 48, c4 = (i - r * 48) * 4;
        float4 v = (r < rows) ? *(const float4*)(out + (long)(n0 + r) * FEAT + c4)
                              : make_float4(0.f, 0.f, 0.f, 0.f);
        *(float4*)&s_x[r * SX + c4] = v;
    }
    __syncthreads();

    // row inverse norms: 4 rows per warp
    for (int r = w * 4; r < w * 4 + 4; r++) {
        float ss = 0.f;
        #pragma unroll
        for (int tt = 0; tt < 6; tt++) {
            float v = s_x[r * SX + lane + 32 * tt];
            ss += v * v;
        }
        #pragma unroll
        for (int o = 16; o; o >>= 1) ss += __shfl_xor_sync(0xffffffffu, ss, o);
        if (lane == 0) s_inv[r] = 1.0f / fmaxf(sqrtf(ss), 1e-12f);
    }
    __syncthreads();

    // ---- GEMM1: logits = o @ nproxy^T, warp (mg,ng): 2 m-tiles, 8 n-cols ----
    {
        float d1[2][4];
        #pragma unroll
        for (int mi = 0; mi < 2; mi++)
            #pragma unroll
            for (int q = 0; q < 4; q++) d1[mi][q] = 0.f;
        unsigned b0 = __ldg(&g_npT[t * 64 + 8 * ng + g]);
        unsigned b1 = __ldg(&g_npT[(t + 4) * 64 + 8 * ng + g]);
        for (int k0 = 0; k0 < FEAT; k0 += 8) {
            unsigned nb0 = 0, nb1 = 0;
            if (k0 + 8 < FEAT) {
                nb0 = __ldg(&g_npT[(k0 + 8 + t) * 64 + 8 * ng + g]);
                nb1 = __ldg(&g_npT[(k0 + 12 + t) * 64 + 8 * ng + g]);
            }
            unsigned bb[2] = {b0, b1};
            #pragma unroll
            for (int mi = 0; mi < 2; mi++) {
                int r0 = 16 * (2 * mg + mi) + g;
                unsigned a[4];
                a[0] = f2tf(s_x[r0 * SX + k0 + t]);
                a[1] = f2tf(s_x[(r0 + 8) * SX + k0 + t]);
                a[2] = f2tf(s_x[r0 * SX + k0 + t + 4]);
                a[3] = f2tf(s_x[(r0 + 8) * SX + k0 + t + 4]);
                mma8(d1[mi], a, bb);
            }
            b0 = nb0; b1 = nb1;
        }
        #pragma unroll
        for (int mi = 0; mi < 2; mi++) {
            int r0 = 16 * (2 * mg + mi) + g;
            int c = 8 * ng + 2 * t;
            float i0 = s_inv[r0], i1 = s_inv[r0 + 8];
            s_p[r0 * SP + c]       = d1[mi][0] * i0;
            s_p[r0 * SP + c + 1]   = d1[mi][1] * i0;
            s_p[(r0 + 8) * SP + c]     = d1[mi][2] * i1;
            s_p[(r0 + 8) * SP + c + 1] = d1[mi][3] * i1;
        }
    }
    __syncthreads();

    // softmax over 64 per row: 4 rows per warp
    for (int r = w * 4; r < w * 4 + 4; r++) {
        float v0 = s_p[r * SP + lane];
        float v1 = s_p[r * SP + 32 + lane];
        float mx = fmaxf(v0, v1);
        #pragma unroll
        for (int o = 16; o; o >>= 1) mx = fmaxf(mx, __shfl_xor_sync(0xffffffffu, mx, o));
        float e0 = expf(v0 - mx), e1 = expf(v1 - mx);
        float sm = e0 + e1;
        #pragma unroll
        for (int o = 16; o; o >>= 1) sm += __shfl_xor_sync(0xffffffffu, sm, o);
        float invs = 1.0f / sm;
        s_p[r * SP + lane] = e0 * invs;
        s_p[r * SP + 32 + lane] = e1 * invs;
    }
    __syncthreads();

    // ---- GEMM2: pf = o - P @ proxy (in-place), cols [24ng, 24ng+24) ----
    {
        float d2[3][2][4];
        #pragma unroll
        for (int ni = 0; ni < 3; ni++)
            #pragma unroll
            for (int mi = 0; mi < 2; mi++)
                #pragma unroll
                for (int q = 0; q < 4; q++) d2[ni][mi][q] = 0.f;
        #pragma unroll 2
        for (int k0 = 0; k0 < 64; k0 += 8) {
            unsigned a[2][4];
            #pragma unroll
            for (int mi = 0; mi < 2; mi++) {
                int r0 = 16 * (2 * mg + mi) + g;
                a[mi][0] = f2tf(s_p[r0 * SP + k0 + t]);
                a[mi][1] = f2tf(s_p[(r0 + 8) * SP + k0 + t]);
                a[mi][2] = f2tf(s_p[r0 * SP + k0 + t + 4]);
                a[mi][3] = f2tf(s_p[(r0 + 8) * SP + k0 + t + 4]);
            }
            #pragma unroll
            for (int ni = 0; ni < 3; ni++) {
                int cb = 24 * ng + 8 * ni + g;
                unsigned b[2];
                b[0] = __ldg(&g_prx[(k0 + t) * FEAT + cb]);
                b[1] = __ldg(&g_prx[(k0 + t + 4) * FEAT + cb]);
                #pragma unroll
                for (int mi = 0; mi < 2; mi++) mma8(d2[ni][mi], a[mi], b);
            }
        }
        #pragma unroll
        for (int ni = 0; ni < 3; ni++) {
            int c = 24 * ng + 8 * ni + 2 * t;
            #pragma unroll
            for (int mi = 0; mi < 2; mi++) {
                int r0 = 16 * (2 * mg + mi) + g;
                s_x[r0 * SX + c]       -= d2[ni][mi][0];
                s_x[r0 * SX + c + 1]   -= d2[ni][mi][1];
                s_x[(r0 + 8) * SX + c]     -= d2[ni][mi][2];
                s_x[(r0 + 8) * SX + c + 1] -= d2[ni][mi][3];
            }
        }
    }
    __syncthreads();

    // ---- GEMM3: pf @ W^T + b -> sigmoid -> blend -> global ----
    {
        float d3[3][2][4];
        #pragma unroll
        for (int ni = 0; ni < 3; ni++)
            #pragma unroll
            for (int mi = 0; mi < 2; mi++)
                #pragma unroll
                for (int q = 0; q < 4; q++) d3[ni][mi][q] = 0.f;
        unsigned b[3][2];
        #pragma unroll
        for (int ni = 0; ni < 3; ni++) {
            int cb = 24 * ng + 8 * ni + g;
            b[ni][0] = __ldg(&g_Wt[t * FEAT + cb]);
            b[ni][1] = __ldg(&g_Wt[(t + 4) * FEAT + cb]);
        }
        for (int k0 = 0; k0 < FEAT; k0 += 8) {
            unsigned nb[3][2];
            if (k0 + 8 < FEAT) {
                #pragma unroll
                for (int ni = 0; ni < 3; ni++) {
                    int cb = 24 * ng + 8 * ni + g;
                    nb[ni][0] = __ldg(&g_Wt[(k0 + 8 + t) * FEAT + cb]);
                    nb[ni][1] = __ldg(&g_Wt[(k0 + 12 + t) * FEAT + cb]);
                }
            }
            unsigned a[2][4];
            #pragma unroll
            for (int mi = 0; mi < 2; mi++) {
                int r0 = 16 * (2 * mg + mi) + g;
                a[mi][0] = f2tf(s_x[r0 * SX + k0 + t]);
                a[mi][1] = f2tf(s_x[(r0 + 8) * SX + k0 + t]);
                a[mi][2] = f2tf(s_x[r0 * SX + k0 + t + 4]);
                a[mi][3] = f2tf(s_x[(r0 + 8) * SX + k0 + t + 4]);
            }
            #pragma unroll
            for (int ni = 0; ni < 3; ni++)
                #pragma unroll
                for (int mi = 0; mi < 2; mi++) mma8(d3[ni][mi], a[mi], b[ni]);
            if (k0 + 8 < FEAT) {
                #pragma unroll
                for (int ni = 0; ni < 3; ni++) { b[ni][0] = nb[ni][0]; b[ni][1] = nb[ni][1]; }
            }
        }
        #pragma unroll
        for (int ni = 0; ni < 3; ni++) {
            int c = 24 * ng + 8 * ni + 2 * t;
            float b0 = __ldg(gate_b + c), b1 = __ldg(gate_b + c + 1);
            #pragma unroll
            for (int mi = 0; mi < 2; mi++) {
                int r0 = 16 * (2 * mg + mi) + g;
                #pragma unroll
                for (int half = 0; half < 2; half++) {
                    int r = r0 + 8 * half;
                    if (r >= rows) continue;
                    float p0 = d3[ni][mi][2 * half]     + b0;
                    float p1 = d3[ni][mi][2 * half + 1] + b1;
                    float g0 = 1.0f / (1.0f + expf(-p0));
                    float g1 = 1.0f / (1.0f + expf(-p1));
                    float2 o2 = *(const float2*)(out + (long)(n0 + r) * FEAT + c);
                    float pf0 = s_x[r * SX + c];
                    float pf1 = s_x[r * SX + c + 1];
                    float2 res = make_float2(g0 * o2.x + (1.0f - g0) * pf0,
                                             g1 * o2.y + (1.0f - g1) * pf1);
                    *(float2*)(out + (long)(n0 + r) * FEAT + c) = res;
                }
            }
        }
    }
}

extern "C" void kernel_launch(void* const* d_in, const int* in_sizes, int n_in,
                              void* d_out, int out_size) {
    const float* features     = (const float*)d_in[0];   // [N,64]
    const float* rel_emb      = (const float*)d_in[1];   // [R,64]
    const float* proxy        = (const float*)d_in[2];   // [64,192]
    const float* gate_w       = (const float*)d_in[3];   // [192,192]
    const float* gate_b       = (const float*)d_in[4];   // [192]
    const float* attn_kernels = (const float*)d_in[5];   // [2,64]
    const int*   adj          = (const int*)d_in[6];     // [2,E]
    const int*   r_index      = (const int*)d_in[7];     // [2,E]
    const float* r_val        = (const float*)d_in[8];   // [E]
    float* out = (float*)d_out;                          // [N,192]

    const int* src = adj + E_EDGES;
    const int* rid = r_index + E_EDGES;

    prep_kernel<<<(564 * 32 + 255) / 256, 256>>>(rel_emb, attn_kernels, proxy);
    convtab_kernel<<<(FEAT * FEAT + 64 * FEAT + 255) / 256, 256>>>(gate_w, proxy);

    tanh_kernel<<<(N_NODES * 16 + 255) / 256, 256>>>(features, out);

    int lgrid = (N_NODES * 32 + 255) / 256;
    layer_kernel<<<lgrid, 256>>>(out, src, rid, r_val, 0);
    layer_kernel<<<lgrid, 256>>>(out, src, rid, r_val, 1);

    size_t smem = (size_t)(NT * SX + NT * SP + NT) * sizeof(float);
    cudaFuncSetAttribute(final_kernel, cudaFuncAttributeMaxDynamicSharedMemorySize, (int)smem);
    final_kernel<<<(N_NODES + NT - 1) / NT, 512, smem>>>(out, gate_b);
}

// round 7
// speedup vs baseline: 1.1491x; 1.0564x over previous
#include <cuda_runtime.h>
#include <cuda_bf16.h>
#include <math.h>

#define N_NODES 50000
#define NODE_DIM 64
#define DEPTH 2
#define FEAT 192           // 64*(DEPTH+1)
#define E_EDGES 1200000
#define R_REL 500
#define DEG 24

// ---------------- scratch (device globals: allocation-free) ----------------
__device__ float    g_nrel[R_REL * NODE_DIM];   // l2-normalized rel_emb
__device__ float    g_attW[DEPTH * R_REL];      // per-relation attention logit per layer
__device__ unsigned g_npT[FEAT * 64];           // normalized proxy, transposed [k][n], tf32 bits
__device__ unsigned g_Wt[FEAT * FEAT];          // gate_w transposed [k][c], tf32 bits
__device__ unsigned g_prx[64 * FEAT];           // proxy [k][n], tf32 bits

__device__ __forceinline__ unsigned f2tf(float x) {
    unsigned r;
    asm("cvt.rna.tf32.f32 %0, %1;" : "=r"(r) : "f"(x));
    return r;
}
// tf32 bit pattern is a valid fp32 value (low mantissa bits zeroed)
__device__ __forceinline__ float tf2f(unsigned b) { return __uint_as_float(b); }

// ---------------- prep: normalize rel table + proxy(->transposed tf32) -----
__global__ void prep_kernel(const float* __restrict__ rel_emb,
                            const float* __restrict__ attn_kernels,
                            const float* __restrict__ proxy) {
    int w = (blockIdx.x * blockDim.x + threadIdx.x) >> 5;
    int lane = threadIdx.x & 31;
    if (w < R_REL) {
        float2 v = ((const float2*)(rel_emb + w * NODE_DIM))[lane];
        float ss = v.x * v.x + v.y * v.y;
        #pragma unroll
        for (int o = 16; o; o >>= 1) ss += __shfl_xor_sync(0xffffffffu, ss, o);
        float inv = 1.0f / fmaxf(sqrtf(ss), 1e-12f);
        float2 nv = make_float2(v.x * inv, v.y * inv);
        ((float2*)(g_nrel + w * NODE_DIM))[lane] = nv;
        float2 a0 = ((const float2*)attn_kernels)[lane];
        float2 a1 = ((const float2*)(attn_kernels + NODE_DIM))[lane];
        float d0 = nv.x * a0.x + nv.y * a0.y;
        float d1 = nv.x * a1.x + nv.y * a1.y;
        #pragma unroll
        for (int o = 16; o; o >>= 1) {
            d0 += __shfl_xor_sync(0xffffffffu, d0, o);
            d1 += __shfl_xor_sync(0xffffffffu, d1, o);
        }
        if (lane == 0) { g_attW[w] = d0; g_attW[R_REL + w] = d1; }
    } else if (w < R_REL + 64) {
        int j = w - R_REL;
        float v[6];
        float ss = 0.f;
        #pragma unroll
        for (int t = 0; t < 6; t++) {
            v[t] = proxy[j * FEAT + lane + 32 * t];
            ss += v[t] * v[t];
        }
        #pragma unroll
        for (int o = 16; o; o >>= 1) ss += __shfl_xor_sync(0xffffffffu, ss, o);
        float inv = 1.0f / fmaxf(sqrtf(ss), 1e-12f);
        #pragma unroll
        for (int t = 0; t < 6; t++)
            g_npT[(lane + 32 * t) * 64 + j] = f2tf(v[t] * inv);   // transposed tf32
    }
}

// ---------------- convert gate_w (transposed) + proxy to tf32 tables --------
__global__ void convtab_kernel(const float* __restrict__ gw,
                               const float* __restrict__ proxy) {
    int idx = blockIdx.x * blockDim.x + threadIdx.x;
    if (idx < FEAT * FEAT) {
        int k = idx / FEAT, c = idx - k * FEAT;
        g_Wt[idx] = f2tf(gw[c * FEAT + k]);
    } else if (idx < FEAT * FEAT + 64 * FEAT) {
        int j = idx - FEAT * FEAT;
        g_prx[j] = f2tf(proxy[j]);
    }
}

// ---------------- layer 0 input: outputs[:,0:64] = tanh(features) ----------
__global__ void tanh_kernel(const float* __restrict__ features, float* __restrict__ out) {
    int idx = blockIdx.x * blockDim.x + threadIdx.x;
    if (idx >= N_NODES * 16) return;
    int i = idx >> 4;
    int j4 = (idx & 15) << 2;
    float4 v = *(const float4*)(features + i * NODE_DIM + j4);
    *(float4*)(out + (long)i * FEAT + j4) =
        make_float4(tanhf(v.x), tanhf(v.y), tanhf(v.z), tanhf(v.w));
}

// ---------------- graph attention layer: warp per node ---------------------
// R4 structure (measured best): two edges per iteration via 16-lane halves.
__global__ void __launch_bounds__(256) layer_kernel(
        float* __restrict__ out,
        const int* __restrict__ src,
        const int* __restrict__ rid,
        const float* __restrict__ rval,
        int l) {
    __shared__ int4 s_meta[8 * DEG];            // per-warp edge table
    int wb = threadIdx.x >> 5;
    int w = (blockIdx.x * blockDim.x + threadIdx.x) >> 5;
    int lane = threadIdx.x & 31;
    if (w >= N_NODES) return;
    int base = w * DEG;

    float att = -INFINITY;
    int ms = 0, mr = 0;
    if (lane < DEG) {
        int e = base + lane;
        ms = __ldg(src + e);
        mr = __ldg(rid + e);
        float sgn = __ldg(rval + e) < 0.f ? -1.f : 1.f;
        att = sgn * g_attW[l * R_REL + mr];
    }
    float m = att;
    #pragma unroll
    for (int o = 16; o; o >>= 1) m = fmaxf(m, __shfl_xor_sync(0xffffffffu, m, o));
    float ex = (lane < DEG) ? __expf(att - m) : 0.f;
    float s = ex;
    #pragma unroll
    for (int o = 16; o; o >>= 1) s += __shfl_xor_sync(0xffffffffu, s, o);
    float wgt = ex / s;

    if (lane < DEG)
        s_meta[wb * DEG + lane] = make_int4(ms * FEAT + NODE_DIM * l,
                                            mr * NODE_DIM,
                                            __float_as_int(wgt), 0);
    __syncwarp();

    int half = lane >> 4;
    int q4 = (lane & 15) << 2;
    float4 acc = make_float4(0.f, 0.f, 0.f, 0.f);
    #pragma unroll 4
    for (int i = 0; i < 12; i++) {
        int4 md = s_meta[wb * DEG + 2 * i + half];
        float4 f = *(const float4*)(out + md.x + q4);
        float4 r = *(const float4*)(g_nrel + md.y + q4);
        float d = f.x * r.x + f.y * r.y + f.z * r.z + f.w * r.w;
        #pragma unroll
        for (int o = 8; o; o >>= 1) d += __shfl_xor_sync(0xffffffffu, d, o);
        float we = __int_as_float(md.z);
        float t2 = 2.f * d;
        acc.x += we * (f.x - t2 * r.x);
        acc.y += we * (f.y - t2 * r.y);
        acc.z += we * (f.z - t2 * r.z);
        acc.w += we * (f.w - t2 * r.w);
    }
    acc.x += __shfl_xor_sync(0xffffffffu, acc.x, 16);
    acc.y += __shfl_xor_sync(0xffffffffu, acc.y, 16);
    acc.z += __shfl_xor_sync(0xffffffffu, acc.z, 16);
    acc.w += __shfl_xor_sync(0xffffffffu, acc.w, 16);

    if (half == 0) {
        float* dst = out + (long)w * FEAT + NODE_DIM * (l + 1);
        *(float4*)(dst + q4) = make_float4(tanhf(acc.x), tanhf(acc.y),
                                           tanhf(acc.z), tanhf(acc.w));
    }
}

// ---------------- tf32 mma helper -------------------------------------------
__device__ __forceinline__ void mma8(float* d, const unsigned* a, const unsigned* b) {
    asm volatile(
        "mma.sync.aligned.m16n8k8.row.col.f32.tf32.tf32.f32 "
        "{%0,%1,%2,%3}, {%4,%5,%6,%7}, {%8,%9}, {%0,%1,%2,%3};\n"
        : "+f"(d[0]), "+f"(d[1]), "+f"(d[2]), "+f"(d[3])
        : "r"(a[0]), "r"(a[1]), "r"(a[2]), "r"(a[3]), "r"(b[0]), "r"(b[1]));
}

// ---------------- fused final stage (tensor-core tf32) ----------------------
// 256 threads / 8 warps / 64-node tile.  s_x and s_p hold TF32 BIT PATTERNS
// (valid fp32 values): GEMM mainloops do LDS->MMA with zero cvt instructions.
#define NT 64
#define SX 196
#define SP 68
__global__ void __launch_bounds__(256, 3) final_kernel(
        float* __restrict__ out,
        const float* __restrict__ gate_b) {
    extern __shared__ float smem[];
    float* s_x   = smem;                    // 64*196  (o as tf32, later pf as tf32)
    float* s_p   = s_x + NT * SX;           // 64*68   (logits fp32 -> probs tf32)
    float* s_inv = s_p + NT * SP;           // 64

    int tid = threadIdx.x;
    int w = tid >> 5, lane = tid & 31;
    int g = lane >> 2, t = lane & 3;
    int n0 = blockIdx.x * NT;
    int rows = N_NODES - n0; if (rows > NT) rows = NT;

    // ---- load o tile, converting to tf32 bits once ----
    for (int i = tid; i < NT * 48; i += 256) {
        int r = i / 48, c4 = (i - r * 48) * 4;
        float4 v = (r < rows) ? *(const float4*)(out + (long)(n0 + r) * FEAT + c4)
                              : make_float4(0.f, 0.f, 0.f, 0.f);
        s_x[r * SX + c4]     = tf2f(f2tf(v.x));
        s_x[r * SX + c4 + 1] = tf2f(f2tf(v.y));
        s_x[r * SX + c4 + 2] = tf2f(f2tf(v.z));
        s_x[r * SX + c4 + 3] = tf2f(f2tf(v.w));
    }
    __syncthreads();

    // ---- row inverse norms (tf32-rounded x; within tolerance) ----
    for (int r = w * 8; r < w * 8 + 8; r++) {
        float ss = 0.f;
        #pragma unroll
        for (int tt = 0; tt < 6; tt++) {
            float v = s_x[r * SX + lane + 32 * tt];
            ss += v * v;
        }
        #pragma unroll
        for (int o = 16; o; o >>= 1) ss += __shfl_xor_sync(0xffffffffu, ss, o);
        if (lane == 0) s_inv[r] = 1.0f / fmaxf(sqrtf(ss), 1e-12f);
    }
    __syncthreads();

    // ---- GEMM1: logits[64x64] = o @ nproxy^T (warp w: n-cols [8w,8w+8)) ----
    {
        float d1[4][4];
        #pragma unroll
        for (int mi = 0; mi < 4; mi++)
            #pragma unroll
            for (int q = 0; q < 4; q++) d1[mi][q] = 0.f;
        for (int k0 = 0; k0 < FEAT; k0 += 8) {
            unsigned b[2];
            b[0] = __ldg(&g_npT[(k0 + t) * 64 + 8 * w + g]);
            b[1] = __ldg(&g_npT[(k0 + t + 4) * 64 + 8 * w + g]);
            #pragma unroll
            for (int mi = 0; mi < 4; mi++) {
                int r0 = 16 * mi + g;
                unsigned a[4];
                a[0] = __float_as_uint(s_x[r0 * SX + k0 + t]);
                a[1] = __float_as_uint(s_x[(r0 + 8) * SX + k0 + t]);
                a[2] = __float_as_uint(s_x[r0 * SX + k0 + t + 4]);
                a[3] = __float_as_uint(s_x[(r0 + 8) * SX + k0 + t + 4]);
                mma8(d1[mi], a, b);
            }
        }
        #pragma unroll
        for (int mi = 0; mi < 4; mi++) {
            int r0 = 16 * mi + g;
            int c = 8 * w + 2 * t;
            float i0 = s_inv[r0], i1 = s_inv[r0 + 8];
            s_p[r0 * SP + c]       = d1[mi][0] * i0;
            s_p[r0 * SP + c + 1]   = d1[mi][1] * i0;
            s_p[(r0 + 8) * SP + c]     = d1[mi][2] * i1;
            s_p[(r0 + 8) * SP + c + 1] = d1[mi][3] * i1;
        }
    }
    __syncthreads();

    // ---- softmax over 64 per row; write probs as tf32 bits ----
    for (int r = w * 8; r < w * 8 + 8; r++) {
        float v0 = s_p[r * SP + lane];
        float v1 = s_p[r * SP + 32 + lane];
        float mx = fmaxf(v0, v1);
        #pragma unroll
        for (int o = 16; o; o >>= 1) mx = fmaxf(mx, __shfl_xor_sync(0xffffffffu, mx, o));
        float e0 = __expf(v0 - mx), e1 = __expf(v1 - mx);
        float sm = e0 + e1;
        #pragma unroll
        for (int o = 16; o; o >>= 1) sm += __shfl_xor_sync(0xffffffffu, sm, o);
        float invs = 1.0f / sm;
        s_p[r * SP + lane]      = tf2f(f2tf(e0 * invs));
        s_p[r * SP + 32 + lane] = tf2f(f2tf(e1 * invs));
    }
    __syncthreads();

    // ---- GEMM2: pf = o - P @ proxy (in-place, tf32 bits) ----
    {
        float d2[3][4][4];
        #pragma unroll
        for (int ni = 0; ni < 3; ni++)
            #pragma unroll
            for (int mi = 0; mi < 4; mi++)
                #pragma unroll
                for (int q = 0; q < 4; q++) d2[ni][mi][q] = 0.f;
        for (int k0 = 0; k0 < 64; k0 += 8) {
            unsigned a[4][4];
            #pragma unroll
            for (int mi = 0; mi < 4; mi++) {
                int r0 = 16 * mi + g;
                a[mi][0] = __float_as_uint(s_p[r0 * SP + k0 + t]);
                a[mi][1] = __float_as_uint(s_p[(r0 + 8) * SP + k0 + t]);
                a[mi][2] = __float_as_uint(s_p[r0 * SP + k0 + t + 4]);
                a[mi][3] = __float_as_uint(s_p[(r0 + 8) * SP + k0 + t + 4]);
            }
            #pragma unroll
            for (int ni = 0; ni < 3; ni++) {
                int cb = 24 * w + 8 * ni + g;
                unsigned b[2];
                b[0] = __ldg(&g_prx[(k0 + t) * FEAT + cb]);
                b[1] = __ldg(&g_prx[(k0 + t + 4) * FEAT + cb]);
                #pragma unroll
                for (int mi = 0; mi < 4; mi++) mma8(d2[ni][mi], a[mi], b);
            }
        }
        #pragma unroll
        for (int ni = 0; ni < 3; ni++) {
            int c = 24 * w + 8 * ni + 2 * t;
            #pragma unroll
            for (int mi = 0; mi < 4; mi++) {
                int r0 = 16 * mi + g;
                s_x[r0 * SX + c]       = tf2f(f2tf(s_x[r0 * SX + c]       - d2[ni][mi][0]));
                s_x[r0 * SX + c + 1]   = tf2f(f2tf(s_x[r0 * SX + c + 1]   - d2[ni][mi][1]));
                s_x[(r0 + 8) * SX + c]     = tf2f(f2tf(s_x[(r0 + 8) * SX + c]     - d2[ni][mi][2]));
                s_x[(r0 + 8) * SX + c + 1] = tf2f(f2tf(s_x[(r0 + 8) * SX + c + 1] - d2[ni][mi][3]));
            }
        }
    }
    __syncthreads();

    // ---- GEMM3: pf @ W^T + b -> sigmoid -> blend (o re-read) -> global ----
    {
        float d3[3][4][4];
        #pragma unroll
        for (int ni = 0; ni < 3; ni++)
            #pragma unroll
            for (int mi = 0; mi < 4; mi++)
                #pragma unroll
                for (int q = 0; q < 4; q++) d3[ni][mi][q] = 0.f;
        for (int k0 = 0; k0 < FEAT; k0 += 8) {
            unsigned a[4][4];
            #pragma unroll
            for (int mi = 0; mi < 4; mi++) {
                int r0 = 16 * mi + g;
                a[mi][0] = __float_as_uint(s_x[r0 * SX + k0 + t]);
                a[mi][1] = __float_as_uint(s_x[(r0 + 8) * SX + k0 + t]);
                a[mi][2] = __float_as_uint(s_x[r0 * SX + k0 + t + 4]);
                a[mi][3] = __float_as_uint(s_x[(r0 + 8) * SX + k0 + t + 4]);
            }
            #pragma unroll
            for (int ni = 0; ni < 3; ni++) {
                int cb = 24 * w + 8 * ni + g;
                unsigned b[2];
                b[0] = __ldg(&g_Wt[(k0 + t) * FEAT + cb]);
                b[1] = __ldg(&g_Wt[(k0 + t + 4) * FEAT + cb]);
                #pragma unroll
                for (int mi = 0; mi < 4; mi++) mma8(d3[ni][mi], a[mi], b);
            }
        }
        #pragma unroll
        for (int ni = 0; ni < 3; ni++) {
            int c = 24 * w + 8 * ni + 2 * t;
            float b0 = __ldg(gate_b + c), b1 = __ldg(gate_b + c + 1);
            #pragma unroll
            for (int mi = 0; mi < 4; mi++) {
                int r0 = 16 * mi + g;
                #pragma unroll
                for (int half = 0; half < 2; half++) {
                    int r = r0 + 8 * half;
                    if (r >= rows) continue;
                    float p0 = d3[ni][mi][2 * half]     + b0;
                    float p1 = d3[ni][mi][2 * half + 1] + b1;
                    float g0 = 1.0f / (1.0f + __expf(-p0));
                    float g1 = 1.0f / (1.0f + __expf(-p1));
                    float2 o2 = *(const float2*)(out + (long)(n0 + r) * FEAT + c);
                    float pf0 = s_x[r * SX + c];
                    float pf1 = s_x[r * SX + c + 1];
                    float2 res = make_float2(g0 * o2.x + (1.0f - g0) * pf0,
                                             g1 * o2.y + (1.0f - g1) * pf1);
                    *(float2*)(out + (long)(n0 + r) * FEAT + c) = res;
                }
            }
        }
    }
}

extern "C" void kernel_launch(void* const* d_in, const int* in_sizes, int n_in,
                              void* d_out, int out_size) {
    const float* features     = (const float*)d_in[0];   // [N,64]
    const float* rel_emb      = (const float*)d_in[1];   // [R,64]
    const float* proxy        = (const float*)d_in[2];   // [64,192]
    const float* gate_w       = (const float*)d_in[3];   // [192,192]
    const float* gate_b       = (const float*)d_in[4];   // [192]
    const float* attn_kernels = (const float*)d_in[5];   // [2,64]
    const int*   adj          = (const int*)d_in[6];     // [2,E]
    const int*   r_index      = (const int*)d_in[7];     // [2,E]
    const float* r_val        = (const float*)d_in[8];   // [E]
    float* out = (float*)d_out;                          // [N,192]

    const int* src = adj + E_EDGES;
    const int* rid = r_index + E_EDGES;

    prep_kernel<<<(564 * 32 + 255) / 256, 256>>>(rel_emb, attn_kernels, proxy);
    convtab_kernel<<<(FEAT * FEAT + 64 * FEAT + 255) / 256, 256>>>(gate_w, proxy);

    tanh_kernel<<<(N_NODES * 16 + 255) / 256, 256>>>(features, out);

    int lgrid = (N_NODES * 32 + 255) / 256;
    layer_kernel<<<lgrid, 256>>>(out, src, rid, r_val, 0);
    layer_kernel<<<lgrid, 256>>>(out, src, rid, r_val, 1);

    size_t smem = (size_t)(NT * SX + NT * SP + NT) * sizeof(float);
    cudaFuncSetAttribute(final_kernel, cudaFuncAttributeMaxDynamicSharedMemorySize, (int)smem);
    final_kernel<<<(N_NODES + NT - 1) / NT, 256, smem>>>(out, gate_b);
}

// round 8
// speedup vs baseline: 1.2394x; 1.0786x over previous
#include <cuda_runtime.h>
#include <cuda_bf16.h>
#include <math.h>

#define N_NODES 50000
#define NODE_DIM 64
#define DEPTH 2
#define FEAT 192           // 64*(DEPTH+1)
#define E_EDGES 1200000
#define R_REL 500
#define DEG 24

// ---------------- scratch (device globals: allocation-free) ----------------
__device__ float    g_nrel[R_REL * NODE_DIM];   // l2-normalized rel_emb
__device__ float    g_attW[DEPTH * R_REL];      // per-relation attention logit per layer
// packed tf32 fragment-pair tables: index ((k>>3)*ncols + c)*4 + (k&3), pair (k0+t, k0+t+4)
__device__ unsigned g_npT2[2 * (FEAT / 8) * 64 * 4];     // normalized proxy^T
__device__ unsigned g_prx2[2 * 8 * FEAT * 4];            // proxy [k][n] (k=64)
__device__ unsigned g_Wt2[2 * (FEAT / 8) * FEAT * 4];    // gate_w^T [k][c]

__device__ __forceinline__ unsigned f2tf(float x) {
    unsigned r;
    asm("cvt.rna.tf32.f32 %0, %1;" : "=r"(r) : "f"(x));
    return r;
}
__device__ __forceinline__ float tf2f(unsigned b) { return __uint_as_float(b); }
// packed destination slot for value at (k, c) in a table with ncols columns
__device__ __forceinline__ int packslot(int k, int c, int ncols) {
    return (((k >> 3) * ncols + c) * 4 + (k & 3)) * 2 + ((k >> 2) & 1);
}

// ---------------- prep: normalize rel table + proxy(->packed tf32) ---------
__global__ void prep_kernel(const float* __restrict__ rel_emb,
                            const float* __restrict__ attn_kernels,
                            const float* __restrict__ proxy) {
    int w = (blockIdx.x * blockDim.x + threadIdx.x) >> 5;
    int lane = threadIdx.x & 31;
    if (w < R_REL) {
        float2 v = ((const float2*)(rel_emb + w * NODE_DIM))[lane];
        float ss = v.x * v.x + v.y * v.y;
        #pragma unroll
        for (int o = 16; o; o >>= 1) ss += __shfl_xor_sync(0xffffffffu, ss, o);
        float inv = 1.0f / fmaxf(sqrtf(ss), 1e-12f);
        float2 nv = make_float2(v.x * inv, v.y * inv);
        ((float2*)(g_nrel + w * NODE_DIM))[lane] = nv;
        float2 a0 = ((const float2*)attn_kernels)[lane];
        float2 a1 = ((const float2*)(attn_kernels + NODE_DIM))[lane];
        float d0 = nv.x * a0.x + nv.y * a0.y;
        float d1 = nv.x * a1.x + nv.y * a1.y;
        #pragma unroll
        for (int o = 16; o; o >>= 1) {
            d0 += __shfl_xor_sync(0xffffffffu, d0, o);
            d1 += __shfl_xor_sync(0xffffffffu, d1, o);
        }
        if (lane == 0) { g_attW[w] = d0; g_attW[R_REL + w] = d1; }
    } else if (w < R_REL + 64) {
        int j = w - R_REL;
        float v[6];
        float ss = 0.f;
        #pragma unroll
        for (int t = 0; t < 6; t++) {
            v[t] = proxy[j * FEAT + lane + 32 * t];
            ss += v[t] * v[t];
        }
        #pragma unroll
        for (int o = 16; o; o >>= 1) ss += __shfl_xor_sync(0xffffffffu, ss, o);
        float inv = 1.0f / fmaxf(sqrtf(ss), 1e-12f);
        #pragma unroll
        for (int t = 0; t < 6; t++) {
            int k = lane + 32 * t;
            g_npT2[packslot(k, j, 64)] = f2tf(v[t] * inv);
        }
    }
}

// ---------------- pack gate_w (transposed) + proxy into tf32 pair tables ----
__global__ void convtab_kernel(const float* __restrict__ gw,
                               const float* __restrict__ proxy) {
    int idx = blockIdx.x * blockDim.x + threadIdx.x;
    if (idx < FEAT * FEAT) {
        int k = idx / FEAT, c = idx - k * FEAT;
        g_Wt2[packslot(k, c, FEAT)] = f2tf(gw[c * FEAT + k]);
    } else if (idx < FEAT * FEAT + 64 * FEAT) {
        int j = idx - FEAT * FEAT;
        int k = j / FEAT, c = j - k * FEAT;
        g_prx2[packslot(k, c, FEAT)] = f2tf(proxy[k * FEAT + c]);
    }
}

// ---------------- layer 0 input: outputs[:,0:64] = tanh(features) ----------
__global__ void tanh_kernel(const float* __restrict__ features, float* __restrict__ out) {
    int idx = blockIdx.x * blockDim.x + threadIdx.x;
    if (idx >= N_NODES * 16) return;
    int i = idx >> 4;
    int j4 = (idx & 15) << 2;
    float4 v = *(const float4*)(features + i * NODE_DIM + j4);
    *(float4*)(out + (long)i * FEAT + j4) =
        make_float4(tanhf(v.x), tanhf(v.y), tanhf(v.z), tanhf(v.w));
}

// ---------------- graph attention layer: warp per node (measured best) -----
__global__ void __launch_bounds__(256) layer_kernel(
        float* __restrict__ out,
        const int* __restrict__ src,
        const int* __restrict__ rid,
        const float* __restrict__ rval,
        int l) {
    __shared__ int4 s_meta[8 * DEG];
    int wb = threadIdx.x >> 5;
    int w = (blockIdx.x * blockDim.x + threadIdx.x) >> 5;
    int lane = threadIdx.x & 31;
    if (w >= N_NODES) return;
    int base = w * DEG;

    float att = -INFINITY;
    int ms = 0, mr = 0;
    if (lane < DEG) {
        int e = base + lane;
        ms = __ldg(src + e);
        mr = __ldg(rid + e);
        float sgn = __ldg(rval + e) < 0.f ? -1.f : 1.f;
        att = sgn * g_attW[l * R_REL + mr];
    }
    float m = att;
    #pragma unroll
    for (int o = 16; o; o >>= 1) m = fmaxf(m, __shfl_xor_sync(0xffffffffu, m, o));
    float ex = (lane < DEG) ? __expf(att - m) : 0.f;
    float s = ex;
    #pragma unroll
    for (int o = 16; o; o >>= 1) s += __shfl_xor_sync(0xffffffffu, s, o);
    float wgt = ex / s;

    if (lane < DEG)
        s_meta[wb * DEG + lane] = make_int4(ms * FEAT + NODE_DIM * l,
                                            mr * NODE_DIM,
                                            __float_as_int(wgt), 0);
    __syncwarp();

    int half = lane >> 4;
    int q4 = (lane & 15) << 2;
    float4 acc = make_float4(0.f, 0.f, 0.f, 0.f);
    #pragma unroll 4
    for (int i = 0; i < 12; i++) {
        int4 md = s_meta[wb * DEG + 2 * i + half];
        float4 f = *(const float4*)(out + md.x + q4);
        float4 r = *(const float4*)(g_nrel + md.y + q4);
        float d = f.x * r.x + f.y * r.y + f.z * r.z + f.w * r.w;
        #pragma unroll
        for (int o = 8; o; o >>= 1) d += __shfl_xor_sync(0xffffffffu, d, o);
        float we = __int_as_float(md.z);
        float t2 = 2.f * d;
        acc.x += we * (f.x - t2 * r.x);
        acc.y += we * (f.y - t2 * r.y);
        acc.z += we * (f.z - t2 * r.z);
        acc.w += we * (f.w - t2 * r.w);
    }
    acc.x += __shfl_xor_sync(0xffffffffu, acc.x, 16);
    acc.y += __shfl_xor_sync(0xffffffffu, acc.y, 16);
    acc.z += __shfl_xor_sync(0xffffffffu, acc.z, 16);
    acc.w += __shfl_xor_sync(0xffffffffu, acc.w, 16);

    if (half == 0) {
        float* dst = out + (long)w * FEAT + NODE_DIM * (l + 1);
        *(float4*)(dst + q4) = make_float4(tanhf(acc.x), tanhf(acc.y),
                                           tanhf(acc.z), tanhf(acc.w));
    }
}

// ---------------- tf32 mma helper -------------------------------------------
__device__ __forceinline__ void mma8(float* d, const unsigned* a, const unsigned* b) {
    asm volatile(
        "mma.sync.aligned.m16n8k8.row.col.f32.tf32.tf32.f32 "
        "{%0,%1,%2,%3}, {%4,%5,%6,%7}, {%8,%9}, {%0,%1,%2,%3};\n"
        : "+f"(d[0]), "+f"(d[1]), "+f"(d[2]), "+f"(d[3])
        : "r"(a[0]), "r"(a[1]), "r"(a[2]), "r"(a[3]), "r"(b[0]), "r"(b[1]));
}

// ---------------- fused final stage (tensor-core tf32, pipelined B) ---------
#define NT 64
#define SX 196
#define SP 68
__global__ void __launch_bounds__(256, 3) final_kernel(
        float* __restrict__ out,
        const float* __restrict__ gate_b) {
    extern __shared__ float smem[];
    float* s_x   = smem;                    // 64*196  (o tf32, later pf tf32)
    float* s_p   = s_x + NT * SX;           // 64*68
    float* s_inv = s_p + NT * SP;           // 64

    int tid = threadIdx.x;
    int w = tid >> 5, lane = tid & 31;
    int g = lane >> 2, t = lane & 3;
    int n0 = blockIdx.x * NT;
    int rows = N_NODES - n0; if (rows > NT) rows = NT;

    for (int i = tid; i < NT * 48; i += 256) {
        int r = i / 48, c4 = (i - r * 48) * 4;
        float4 v = (r < rows) ? *(const float4*)(out + (long)(n0 + r) * FEAT + c4)
                              : make_float4(0.f, 0.f, 0.f, 0.f);
        s_x[r * SX + c4]     = tf2f(f2tf(v.x));
        s_x[r * SX + c4 + 1] = tf2f(f2tf(v.y));
        s_x[r * SX + c4 + 2] = tf2f(f2tf(v.z));
        s_x[r * SX + c4 + 3] = tf2f(f2tf(v.w));
    }
    __syncthreads();

    for (int r = w * 8; r < w * 8 + 8; r++) {
        float ss = 0.f;
        #pragma unroll
        for (int tt = 0; tt < 6; tt++) {
            float v = s_x[r * SX + lane + 32 * tt];
            ss += v * v;
        }
        #pragma unroll
        for (int o = 16; o; o >>= 1) ss += __shfl_xor_sync(0xffffffffu, ss, o);
        if (lane == 0) s_inv[r] = 1.0f / fmaxf(sqrtf(ss), 1e-12f);
    }
    __syncthreads();

    // ---- GEMM1: logits = o @ nproxy^T, depth-2 B prefetch ----
    {
        float d1[4][4];
        #pragma unroll
        for (int mi = 0; mi < 4; mi++)
            #pragma unroll
            for (int q = 0; q < 4; q++) d1[mi][q] = 0.f;
        const uint2* B = (const uint2*)g_npT2;
        int bi = (8 * w + g) * 4 + t;               // + kk*256
        uint2 bc = __ldg(B + bi);
        uint2 bn = __ldg(B + 256 + bi);
        #pragma unroll 2
        for (int kk = 0; kk < 24; kk++) {
            uint2 bf = make_uint2(0u, 0u);
            if (kk + 2 < 24) bf = __ldg(B + (kk + 2) * 256 + bi);
            unsigned bb[2] = {bc.x, bc.y};
            int k0 = kk * 8;
            #pragma unroll
            for (int mi = 0; mi < 4; mi++) {
                int r0 = 16 * mi + g;
                unsigned a[4];
                a[0] = __float_as_uint(s_x[r0 * SX + k0 + t]);
                a[1] = __float_as_uint(s_x[(r0 + 8) * SX + k0 + t]);
                a[2] = __float_as_uint(s_x[r0 * SX + k0 + t + 4]);
                a[3] = __float_as_uint(s_x[(r0 + 8) * SX + k0 + t + 4]);
                mma8(d1[mi], a, bb);
            }
            bc = bn; bn = bf;
        }
        #pragma unroll
        for (int mi = 0; mi < 4; mi++) {
            int r0 = 16 * mi + g;
            int c = 8 * w + 2 * t;
            float i0 = s_inv[r0], i1 = s_inv[r0 + 8];
            s_p[r0 * SP + c]       = d1[mi][0] * i0;
            s_p[r0 * SP + c + 1]   = d1[mi][1] * i0;
            s_p[(r0 + 8) * SP + c]     = d1[mi][2] * i1;
            s_p[(r0 + 8) * SP + c + 1] = d1[mi][3] * i1;
        }
    }
    __syncthreads();

    for (int r = w * 8; r < w * 8 + 8; r++) {
        float v0 = s_p[r * SP + lane];
        float v1 = s_p[r * SP + 32 + lane];
        float mx = fmaxf(v0, v1);
        #pragma unroll
        for (int o = 16; o; o >>= 1) mx = fmaxf(mx, __shfl_xor_sync(0xffffffffu, mx, o));
        float e0 = __expf(v0 - mx), e1 = __expf(v1 - mx);
        float sm = e0 + e1;
        #pragma unroll
        for (int o = 16; o; o >>= 1) sm += __shfl_xor_sync(0xffffffffu, sm, o);
        float invs = 1.0f / sm;
        s_p[r * SP + lane]      = tf2f(f2tf(e0 * invs));
        s_p[r * SP + 32 + lane] = tf2f(f2tf(e1 * invs));
    }
    __syncthreads();

    // ---- GEMM2: pf = o - P @ proxy (in-place), depth-1 B prefetch ----
    {
        float d2[3][4][4];
        #pragma unroll
        for (int ni = 0; ni < 3; ni++)
            #pragma unroll
            for (int mi = 0; mi < 4; mi++)
                #pragma unroll
                for (int q = 0; q < 4; q++) d2[ni][mi][q] = 0.f;
        const uint2* B = (const uint2*)g_prx2;
        int bi = (24 * w + g) * 4 + t;              // + ni*32 + kk*768
        uint2 bc[3], bn[3];
        #pragma unroll
        for (int ni = 0; ni < 3; ni++) bc[ni] = __ldg(B + bi + 32 * ni);
        for (int kk = 0; kk < 8; kk++) {
            if (kk + 1 < 8) {
                #pragma unroll
                for (int ni = 0; ni < 3; ni++)
                    bn[ni] = __ldg(B + (kk + 1) * 768 + bi + 32 * ni);
            }
            int k0 = kk * 8;
            unsigned a[4][4];
            #pragma unroll
            for (int mi = 0; mi < 4; mi++) {
                int r0 = 16 * mi + g;
                a[mi][0] = __float_as_uint(s_p[r0 * SP + k0 + t]);
                a[mi][1] = __float_as_uint(s_p[(r0 + 8) * SP + k0 + t]);
                a[mi][2] = __float_as_uint(s_p[r0 * SP + k0 + t + 4]);
                a[mi][3] = __float_as_uint(s_p[(r0 + 8) * SP + k0 + t + 4]);
            }
            #pragma unroll
            for (int ni = 0; ni < 3; ni++) {
                unsigned bb[2] = {bc[ni].x, bc[ni].y};
                #pragma unroll
                for (int mi = 0; mi < 4; mi++) mma8(d2[ni][mi], a[mi], bb);
            }
            #pragma unroll
            for (int ni = 0; ni < 3; ni++) bc[ni] = bn[ni];
        }
        #pragma unroll
        for (int ni = 0; ni < 3; ni++) {
            int c = 24 * w + 8 * ni + 2 * t;
            #pragma unroll
            for (int mi = 0; mi < 4; mi++) {
                int r0 = 16 * mi + g;
                s_x[r0 * SX + c]       = tf2f(f2tf(s_x[r0 * SX + c]       - d2[ni][mi][0]));
                s_x[r0 * SX + c + 1]   = tf2f(f2tf(s_x[r0 * SX + c + 1]   - d2[ni][mi][1]));
                s_x[(r0 + 8) * SX + c]     = tf2f(f2tf(s_x[(r0 + 8) * SX + c]     - d2[ni][mi][2]));
                s_x[(r0 + 8) * SX + c + 1] = tf2f(f2tf(s_x[(r0 + 8) * SX + c + 1] - d2[ni][mi][3]));
            }
        }
    }
    __syncthreads();

    // ---- GEMM3: pf @ W^T + b -> sigmoid -> blend, depth-1 B prefetch ----
    {
        float d3[3][4][4];
        #pragma unroll
        for (int ni = 0; ni < 3; ni++)
            #pragma unroll
            for (int mi = 0; mi < 4; mi++)
                #pragma unroll
                for (int q = 0; q < 4; q++) d3[ni][mi][q] = 0.f;
        const uint2* B = (const uint2*)g_Wt2;
        int bi = (24 * w + g) * 4 + t;              // + ni*32 + kk*768
        uint2 bc[3], bn[3];
        #pragma unroll
        for (int ni = 0; ni < 3; ni++) bc[ni] = __ldg(B + bi + 32 * ni);
        #pragma unroll 2
        for (int kk = 0; kk < 24; kk++) {
            if (kk + 1 < 24) {
                #pragma unroll
                for (int ni = 0; ni < 3; ni++)
                    bn[ni] = __ldg(B + (kk + 1) * 768 + bi + 32 * ni);
            }
            int k0 = kk * 8;
            unsigned a[4][4];
            #pragma unroll
            for (int mi = 0; mi < 4; mi++) {
                int r0 = 16 * mi + g;
                a[mi][0] = __float_as_uint(s_x[r0 * SX + k0 + t]);
                a[mi][1] = __float_as_uint(s_x[(r0 + 8) * SX + k0 + t]);
                a[mi][2] = __float_as_uint(s_x[r0 * SX + k0 + t + 4]);
                a[mi][3] = __float_as_uint(s_x[(r0 + 8) * SX + k0 + t + 4]);
            }
            #pragma unroll
            for (int ni = 0; ni < 3; ni++) {
                unsigned bb[2] = {bc[ni].x, bc[ni].y};
                #pragma unroll
                for (int mi = 0; mi < 4; mi++) mma8(d3[ni][mi], a[mi], bb);
            }
            #pragma unroll
            for (int ni = 0; ni < 3; ni++) bc[ni] = bn[ni];
        }
        #pragma unroll
        for (int ni = 0; ni < 3; ni++) {
            int c = 24 * w + 8 * ni + 2 * t;
            float b0 = __ldg(gate_b + c), b1 = __ldg(gate_b + c + 1);
            #pragma unroll
            for (int mi = 0; mi < 4; mi++) {
                int r0 = 16 * mi + g;
                #pragma unroll
                for (int half = 0; half < 2; half++) {
                    int r = r0 + 8 * half;
                    if (r >= rows) continue;
                    float p0 = d3[ni][mi][2 * half]     + b0;
                    float p1 = d3[ni][mi][2 * half + 1] + b1;
                    float g0 = 1.0f / (1.0f + __expf(-p0));
                    float g1 = 1.0f / (1.0f + __expf(-p1));
                    float2 o2 = *(const float2*)(out + (long)(n0 + r) * FEAT + c);
                    float pf0 = s_x[r * SX + c];
                    float pf1 = s_x[r * SX + c + 1];
                    float2 res = make_float2(g0 * o2.x + (1.0f - g0) * pf0,
                                             g1 * o2.y + (1.0f - g1) * pf1);
                    *(float2*)(out + (long)(n0 + r) * FEAT + c) = res;
                }
            }
        }
    }
}

extern "C" void kernel_launch(void* const* d_in, const int* in_sizes, int n_in,
                              void* d_out, int out_size) {
    const float* features     = (const float*)d_in[0];   // [N,64]
    const float* rel_emb      = (const float*)d_in[1];   // [R,64]
    const float* proxy        = (const float*)d_in[2];   // [64,192]
    const float* gate_w       = (const float*)d_in[3];   // [192,192]
    const float* gate_b       = (const float*)d_in[4];   // [192]
    const float* attn_kernels = (const float*)d_in[5];   // [2,64]
    const int*   adj          = (const int*)d_in[6];     // [2,E]
    const int*   r_index      = (const int*)d_in[7];     // [2,E]
    const float* r_val        = (const float*)d_in[8];   // [E]
    float* out = (float*)d_out;                          // [N,192]

    const int* src = adj + E_EDGES;
    const int* rid = r_index + E_EDGES;

    prep_kernel<<<(564 * 32 + 255) / 256, 256>>>(rel_emb, attn_kernels, proxy);
    convtab_kernel<<<(FEAT * FEAT + 64 * FEAT + 255) / 256, 256>>>(gate_w, proxy);

    tanh_kernel<<<(N_NODES * 16 + 255) / 256, 256>>>(features, out);

    int lgrid = (N_NODES * 32 + 255) / 256;
    layer_kernel<<<lgrid, 256>>>(out, src, rid, r_val, 0);
    layer_kernel<<<lgrid, 256>>>(out, src, rid, r_val, 1);

    size_t smem = (size_t)(NT * SX + NT * SP + NT) * sizeof(float);
    cudaFuncSetAttribute(final_kernel, cudaFuncAttributeMaxDynamicSharedMemorySize, (int)smem);
    final_kernel<<<(N_NODES + NT - 1) / NT, 256, smem>>>(out, gate_b);
}

// round 9
// speedup vs baseline: 1.2500x; 1.0086x over previous
#include <cuda_runtime.h>
#include <cuda_bf16.h>
#include <math.h>

#define N_NODES 50000
#define NODE_DIM 64
#define DEPTH 2
#define FEAT 192           // 64*(DEPTH+1)
#define E_EDGES 1200000
#define R_REL 500
#define DEG 24

// ---------------- scratch (device globals: allocation-free) ----------------
__device__ float    g_nrel[R_REL * NODE_DIM];   // l2-normalized rel_emb
__device__ float    g_attW[DEPTH * R_REL];      // per-relation attention logit per layer
// packed tf32 fragment-pair tables: pair (k0+t, k0+t+4) per uint2
__device__ unsigned g_npT2[2 * (FEAT / 8) * 64 * 4];     // normalized proxy^T
__device__ unsigned g_prx2[2 * 8 * FEAT * 4];            // proxy [k][n] (k=64)
__device__ unsigned g_Wt2[2 * (FEAT / 8) * FEAT * 4];    // gate_w^T [k][c]

__device__ __forceinline__ unsigned f2tf(float x) {
    unsigned r;
    asm("cvt.rna.tf32.f32 %0, %1;" : "=r"(r) : "f"(x));
    return r;
}
__device__ __forceinline__ float tf2f(unsigned b) { return __uint_as_float(b); }
__device__ __forceinline__ int packslot(int k, int c, int ncols) {
    return (((k >> 3) * ncols + c) * 4 + (k & 3)) * 2 + ((k >> 2) & 1);
}

// ---------------- prep: normalize rel table + proxy(->packed tf32) ---------
__global__ void prep_kernel(const float* __restrict__ rel_emb,
                            const float* __restrict__ attn_kernels,
                            const float* __restrict__ proxy) {
    int w = (blockIdx.x * blockDim.x + threadIdx.x) >> 5;
    int lane = threadIdx.x & 31;
    if (w < R_REL) {
        float2 v = ((const float2*)(rel_emb + w * NODE_DIM))[lane];
        float ss = v.x * v.x + v.y * v.y;
        #pragma unroll
        for (int o = 16; o; o >>= 1) ss += __shfl_xor_sync(0xffffffffu, ss, o);
        float inv = 1.0f / fmaxf(sqrtf(ss), 1e-12f);
        float2 nv = make_float2(v.x * inv, v.y * inv);
        ((float2*)(g_nrel + w * NODE_DIM))[lane] = nv;
        float2 a0 = ((const float2*)attn_kernels)[lane];
        float2 a1 = ((const float2*)(attn_kernels + NODE_DIM))[lane];
        float d0 = nv.x * a0.x + nv.y * a0.y;
        float d1 = nv.x * a1.x + nv.y * a1.y;
        #pragma unroll
        for (int o = 16; o; o >>= 1) {
            d0 += __shfl_xor_sync(0xffffffffu, d0, o);
            d1 += __shfl_xor_sync(0xffffffffu, d1, o);
        }
        if (lane == 0) { g_attW[w] = d0; g_attW[R_REL + w] = d1; }
    } else if (w < R_REL + 64) {
        int j = w - R_REL;
        float v[6];
        float ss = 0.f;
        #pragma unroll
        for (int t = 0; t < 6; t++) {
            v[t] = proxy[j * FEAT + lane + 32 * t];
            ss += v[t] * v[t];
        }
        #pragma unroll
        for (int o = 16; o; o >>= 1) ss += __shfl_xor_sync(0xffffffffu, ss, o);
        float inv = 1.0f / fmaxf(sqrtf(ss), 1e-12f);
        #pragma unroll
        for (int t = 0; t < 6; t++) {
            int k = lane + 32 * t;
            g_npT2[packslot(k, j, 64)] = f2tf(v[t] * inv);
        }
    }
}

// ---------------- pack gate_w (transposed) + proxy into tf32 pair tables ----
__global__ void convtab_kernel(const float* __restrict__ gw,
                               const float* __restrict__ proxy) {
    int idx = blockIdx.x * blockDim.x + threadIdx.x;
    if (idx < FEAT * FEAT) {
        int k = idx / FEAT, c = idx - k * FEAT;
        g_Wt2[packslot(k, c, FEAT)] = f2tf(gw[c * FEAT + k]);
    } else if (idx < FEAT * FEAT + 64 * FEAT) {
        int j = idx - FEAT * FEAT;
        int k = j / FEAT, c = j - k * FEAT;
        g_prx2[packslot(k, c, FEAT)] = f2tf(proxy[k * FEAT + c]);
    }
}

// ---------------- layer 0 input: outputs[:,0:64] = tanh(features) ----------
__global__ void tanh_kernel(const float* __restrict__ features, float* __restrict__ out) {
    int idx = blockIdx.x * blockDim.x + threadIdx.x;
    if (idx >= N_NODES * 16) return;
    int i = idx >> 4;
    int j4 = (idx & 15) << 2;
    float4 v = *(const float4*)(features + i * NODE_DIM + j4);
    *(float4*)(out + (long)i * FEAT + j4) =
        make_float4(tanhf(v.x), tanhf(v.y), tanhf(v.z), tanhf(v.w));
}

// ---------------- graph attention layer: warp per node (measured best) -----
__global__ void __launch_bounds__(256) layer_kernel(
        float* __restrict__ out,
        const int* __restrict__ src,
        const int* __restrict__ rid,
        const float* __restrict__ rval,
        int l) {
    __shared__ int4 s_meta[8 * DEG];
    int wb = threadIdx.x >> 5;
    int w = (blockIdx.x * blockDim.x + threadIdx.x) >> 5;
    int lane = threadIdx.x & 31;
    if (w >= N_NODES) return;
    int base = w * DEG;

    float att = -INFINITY;
    int ms = 0, mr = 0;
    if (lane < DEG) {
        int e = base + lane;
        ms = __ldg(src + e);
        mr = __ldg(rid + e);
        float sgn = __ldg(rval + e) < 0.f ? -1.f : 1.f;
        att = sgn * g_attW[l * R_REL + mr];
    }
    float m = att;
    #pragma unroll
    for (int o = 16; o; o >>= 1) m = fmaxf(m, __shfl_xor_sync(0xffffffffu, m, o));
    float ex = (lane < DEG) ? __expf(att - m) : 0.f;
    float s = ex;
    #pragma unroll
    for (int o = 16; o; o >>= 1) s += __shfl_xor_sync(0xffffffffu, s, o);
    float wgt = ex / s;

    if (lane < DEG)
        s_meta[wb * DEG + lane] = make_int4(ms * FEAT + NODE_DIM * l,
                                            mr * NODE_DIM,
                                            __float_as_int(wgt), 0);
    __syncwarp();

    int half = lane >> 4;
    int q4 = (lane & 15) << 2;
    float4 acc = make_float4(0.f, 0.f, 0.f, 0.f);
    #pragma unroll 4
    for (int i = 0; i < 12; i++) {
        int4 md = s_meta[wb * DEG + 2 * i + half];
        float4 f = *(const float4*)(out + md.x + q4);
        float4 r = *(const float4*)(g_nrel + md.y + q4);
        float d = f.x * r.x + f.y * r.y + f.z * r.z + f.w * r.w;
        #pragma unroll
        for (int o = 8; o; o >>= 1) d += __shfl_xor_sync(0xffffffffu, d, o);
        float we = __int_as_float(md.z);
        float t2 = 2.f * d;
        acc.x += we * (f.x - t2 * r.x);
        acc.y += we * (f.y - t2 * r.y);
        acc.z += we * (f.z - t2 * r.z);
        acc.w += we * (f.w - t2 * r.w);
    }
    acc.x += __shfl_xor_sync(0xffffffffu, acc.x, 16);
    acc.y += __shfl_xor_sync(0xffffffffu, acc.y, 16);
    acc.z += __shfl_xor_sync(0xffffffffu, acc.z, 16);
    acc.w += __shfl_xor_sync(0xffffffffu, acc.w, 16);

    if (half == 0) {
        float* dst = out + (long)w * FEAT + NODE_DIM * (l + 1);
        *(float4*)(dst + q4) = make_float4(tanhf(acc.x), tanhf(acc.y),
                                           tanhf(acc.z), tanhf(acc.w));
    }
}

// ---------------- tf32 mma helper -------------------------------------------
__device__ __forceinline__ void mma8(float* d, const unsigned* a, const unsigned* b) {
    asm volatile(
        "mma.sync.aligned.m16n8k8.row.col.f32.tf32.tf32.f32 "
        "{%0,%1,%2,%3}, {%4,%5,%6,%7}, {%8,%9}, {%0,%1,%2,%3};\n"
        : "+f"(d[0]), "+f"(d[1]), "+f"(d[2]), "+f"(d[3])
        : "r"(a[0]), "r"(a[1]), "r"(a[2]), "r"(a[3]), "r"(b[0]), "r"(b[1]));
}

// ---------------- fused final stage (tensor-core tf32, pipelined B) ---------
// NT=48 rows/tile -> 50.9 KB smem -> 4 CTAs/SM for more overlapped chains.
#define NT 48
#define MT 3               // m16 tiles per block
#define SX 196
#define SP 68
__global__ void __launch_bounds__(256, 4) final_kernel(
        float* __restrict__ out,
        const float* __restrict__ gate_b) {
    extern __shared__ float smem[];
    float* s_x   = smem;                    // NT*196  (o tf32, later pf tf32)
    float* s_p   = s_x + NT * SX;           // NT*68
    float* s_inv = s_p + NT * SP;           // NT

    int tid = threadIdx.x;
    int w = tid >> 5, lane = tid & 31;
    int g = lane >> 2, t = lane & 3;
    int n0 = blockIdx.x * NT;
    int rows = N_NODES - n0; if (rows > NT) rows = NT;

    for (int i = tid; i < NT * 48; i += 256) {
        int r = i / 48, c4 = (i - r * 48) * 4;
        float4 v = (r < rows) ? *(const float4*)(out + (long)(n0 + r) * FEAT + c4)
                              : make_float4(0.f, 0.f, 0.f, 0.f);
        s_x[r * SX + c4]     = tf2f(f2tf(v.x));
        s_x[r * SX + c4 + 1] = tf2f(f2tf(v.y));
        s_x[r * SX + c4 + 2] = tf2f(f2tf(v.z));
        s_x[r * SX + c4 + 3] = tf2f(f2tf(v.w));
    }
    __syncthreads();

    // ---- row inverse norms: 6 rows per warp ----
    for (int r = w * 6; r < w * 6 + 6; r++) {
        float ss = 0.f;
        #pragma unroll
        for (int tt = 0; tt < 6; tt++) {
            float v = s_x[r * SX + lane + 32 * tt];
            ss += v * v;
        }
        #pragma unroll
        for (int o = 16; o; o >>= 1) ss += __shfl_xor_sync(0xffffffffu, ss, o);
        if (lane == 0) s_inv[r] = 1.0f / fmaxf(sqrtf(ss), 1e-12f);
    }
    __syncthreads();

    // ---- GEMM1: logits[NT x 64] = o @ nproxy^T, depth-2 B prefetch ----
    {
        float d1[MT][4];
        #pragma unroll
        for (int mi = 0; mi < MT; mi++)
            #pragma unroll
            for (int q = 0; q < 4; q++) d1[mi][q] = 0.f;
        const uint2* B = (const uint2*)g_npT2;
        int bi = (8 * w + g) * 4 + t;               // + kk*256
        uint2 bc = __ldg(B + bi);
        uint2 bn = __ldg(B + 256 + bi);
        #pragma unroll 2
        for (int kk = 0; kk < 24; kk++) {
            uint2 bf = make_uint2(0u, 0u);
            if (kk + 2 < 24) bf = __ldg(B + (kk + 2) * 256 + bi);
            unsigned bb[2] = {bc.x, bc.y};
            int k0 = kk * 8;
            #pragma unroll
            for (int mi = 0; mi < MT; mi++) {
                int r0 = 16 * mi + g;
                unsigned a[4];
                a[0] = __float_as_uint(s_x[r0 * SX + k0 + t]);
                a[1] = __float_as_uint(s_x[(r0 + 8) * SX + k0 + t]);
                a[2] = __float_as_uint(s_x[r0 * SX + k0 + t + 4]);
                a[3] = __float_as_uint(s_x[(r0 + 8) * SX + k0 + t + 4]);
                mma8(d1[mi], a, bb);
            }
            bc = bn; bn = bf;
        }
        #pragma unroll
        for (int mi = 0; mi < MT; mi++) {
            int r0 = 16 * mi + g;
            int c = 8 * w + 2 * t;
            float i0 = s_inv[r0], i1 = s_inv[r0 + 8];
            s_p[r0 * SP + c]       = d1[mi][0] * i0;
            s_p[r0 * SP + c + 1]   = d1[mi][1] * i0;
            s_p[(r0 + 8) * SP + c]     = d1[mi][2] * i1;
            s_p[(r0 + 8) * SP + c + 1] = d1[mi][3] * i1;
        }
    }
    __syncthreads();

    // ---- softmax over 64 per row: 6 rows per warp ----
    for (int r = w * 6; r < w * 6 + 6; r++) {
        float v0 = s_p[r * SP + lane];
        float v1 = s_p[r * SP + 32 + lane];
        float mx = fmaxf(v0, v1);
        #pragma unroll
        for (int o = 16; o; o >>= 1) mx = fmaxf(mx, __shfl_xor_sync(0xffffffffu, mx, o));
        float e0 = __expf(v0 - mx), e1 = __expf(v1 - mx);
        float sm = e0 + e1;
        #pragma unroll
        for (int o = 16; o; o >>= 1) sm += __shfl_xor_sync(0xffffffffu, sm, o);
        float invs = 1.0f / sm;
        s_p[r * SP + lane]      = tf2f(f2tf(e0 * invs));
        s_p[r * SP + 32 + lane] = tf2f(f2tf(e1 * invs));
    }
    __syncthreads();

    // ---- GEMM2: pf = o - P @ proxy (in-place), depth-1 B prefetch ----
    {
        float d2[3][MT][4];
        #pragma unroll
        for (int ni = 0; ni < 3; ni++)
            #pragma unroll
            for (int mi = 0; mi < MT; mi++)
                #pragma unroll
                for (int q = 0; q < 4; q++) d2[ni][mi][q] = 0.f;
        const uint2* B = (const uint2*)g_prx2;
        int bi = (24 * w + g) * 4 + t;              // + ni*32 + kk*768
        uint2 bc[3], bn[3];
        #pragma unroll
        for (int ni = 0; ni < 3; ni++) bc[ni] = __ldg(B + bi + 32 * ni);
        for (int kk = 0; kk < 8; kk++) {
            if (kk + 1 < 8) {
                #pragma unroll
                for (int ni = 0; ni < 3; ni++)
                    bn[ni] = __ldg(B + (kk + 1) * 768 + bi + 32 * ni);
            }
            int k0 = kk * 8;
            unsigned a[MT][4];
            #pragma unroll
            for (int mi = 0; mi < MT; mi++) {
                int r0 = 16 * mi + g;
                a[mi][0] = __float_as_uint(s_p[r0 * SP + k0 + t]);
                a[mi][1] = __float_as_uint(s_p[(r0 + 8) * SP + k0 + t]);
                a[mi][2] = __float_as_uint(s_p[r0 * SP + k0 + t + 4]);
                a[mi][3] = __float_as_uint(s_p[(r0 + 8) * SP + k0 + t + 4]);
            }
            #pragma unroll
            for (int ni = 0; ni < 3; ni++) {
                unsigned bb[2] = {bc[ni].x, bc[ni].y};
                #pragma unroll
                for (int mi = 0; mi < MT; mi++) mma8(d2[ni][mi], a[mi], bb);
            }
            #pragma unroll
            for (int ni = 0; ni < 3; ni++) bc[ni] = bn[ni];
        }
        #pragma unroll
        for (int ni = 0; ni < 3; ni++) {
            int c = 24 * w + 8 * ni + 2 * t;
            #pragma unroll
            for (int mi = 0; mi < MT; mi++) {
                int r0 = 16 * mi + g;
                s_x[r0 * SX + c]       = tf2f(f2tf(s_x[r0 * SX + c]       - d2[ni][mi][0]));
                s_x[r0 * SX + c + 1]   = tf2f(f2tf(s_x[r0 * SX + c + 1]   - d2[ni][mi][1]));
                s_x[(r0 + 8) * SX + c]     = tf2f(f2tf(s_x[(r0 + 8) * SX + c]     - d2[ni][mi][2]));
                s_x[(r0 + 8) * SX + c + 1] = tf2f(f2tf(s_x[(r0 + 8) * SX + c + 1] - d2[ni][mi][3]));
            }
        }
    }
    __syncthreads();

    // ---- GEMM3: pf @ W^T + b -> sigmoid -> blend, depth-1 B prefetch ----
    {
        float d3[3][MT][4];
        #pragma unroll
        for (int ni = 0; ni < 3; ni++)
            #pragma unroll
            for (int mi = 0; mi < MT; mi++)
                #pragma unroll
                for (int q = 0; q < 4; q++) d3[ni][mi][q] = 0.f;
        const uint2* B = (const uint2*)g_Wt2;
        int bi = (24 * w + g) * 4 + t;              // + ni*32 + kk*768
        uint2 bc[3], bn[3];
        #pragma unroll
        for (int ni = 0; ni < 3; ni++) bc[ni] = __ldg(B + bi + 32 * ni);
        #pragma unroll 2
        for (int kk = 0; kk < 24; kk++) {
            if (kk + 1 < 24) {
                #pragma unroll
                for (int ni = 0; ni < 3; ni++)
                    bn[ni] = __ldg(B + (kk + 1) * 768 + bi + 32 * ni);
            }
            int k0 = kk * 8;
            unsigned a[MT][4];
            #pragma unroll
            for (int mi = 0; mi < MT; mi++) {
                int r0 = 16 * mi + g;
                a[mi][0] = __float_as_uint(s_x[r0 * SX + k0 + t]);
                a[mi][1] = __float_as_uint(s_x[(r0 + 8) * SX + k0 + t]);
                a[mi][2] = __float_as_uint(s_x[r0 * SX + k0 + t + 4]);
                a[mi][3] = __float_as_uint(s_x[(r0 + 8) * SX + k0 + t + 4]);
            }
            #pragma unroll
            for (int ni = 0; ni < 3; ni++) {
                unsigned bb[2] = {bc[ni].x, bc[ni].y};
                #pragma unroll
                for (int mi = 0; mi < MT; mi++) mma8(d3[ni][mi], a[mi], bb);
            }
            #pragma unroll
            for (int ni = 0; ni < 3; ni++) bc[ni] = bn[ni];
        }
        #pragma unroll
        for (int ni = 0; ni < 3; ni++) {
            int c = 24 * w + 8 * ni + 2 * t;
            float b0 = __ldg(gate_b + c), b1 = __ldg(gate_b + c + 1);
            #pragma unroll
            for (int mi = 0; mi < MT; mi++) {
                int r0 = 16 * mi + g;
                #pragma unroll
                for (int half = 0; half < 2; half++) {
                    int r = r0 + 8 * half;
                    if (r >= rows) continue;
                    float p0 = d3[ni][mi][2 * half]     + b0;
                    float p1 = d3[ni][mi][2 * half + 1] + b1;
                    float g0 = 1.0f / (1.0f + __expf(-p0));
                    float g1 = 1.0f / (1.0f + __expf(-p1));
                    float2 o2 = *(const float2*)(out + (long)(n0 + r) * FEAT + c);
                    float pf0 = s_x[r * SX + c];
                    float pf1 = s_x[r * SX + c + 1];
                    float2 res = make_float2(g0 * o2.x + (1.0f - g0) * pf0,
                                             g1 * o2.y + (1.0f - g1) * pf1);
                    *(float2*)(out + (long)(n0 + r) * FEAT + c) = res;
                }
            }
        }
    }
}

extern "C" void kernel_launch(void* const* d_in, const int* in_sizes, int n_in,
                              void* d_out, int out_size) {
    const float* features     = (const float*)d_in[0];   // [N,64]
    const float* rel_emb      = (const float*)d_in[1];   // [R,64]
    const float* proxy        = (const float*)d_in[2];   // [64,192]
    const float* gate_w       = (const float*)d_in[3];   // [192,192]
    const float* gate_b       = (const float*)d_in[4];   // [192]
    const float* attn_kernels = (const float*)d_in[5];   // [2,64]
    const int*   adj          = (const int*)d_in[6];     // [2,E]
    const int*   r_index      = (const int*)d_in[7];     // [2,E]
    const float* r_val        = (const float*)d_in[8];   // [E]
    float* out = (float*)d_out;                          // [N,192]

    const int* src = adj + E_EDGES;
    const int* rid = r_index + E_EDGES;

    prep_kernel<<<(564 * 32 + 255) / 256, 256>>>(rel_emb, attn_kernels, proxy);
    convtab_kernel<<<(FEAT * FEAT + 64 * FEAT + 255) / 256, 256>>>(gate_w, proxy);

    tanh_kernel<<<(N_NODES * 16 + 255) / 256, 256>>>(features, out);

    int lgrid = (N_NODES * 32 + 255) / 256;
    layer_kernel<<<lgrid, 256>>>(out, src, rid, r_val, 0);
    layer_kernel<<<lgrid, 256>>>(out, src, rid, r_val, 1);

    size_t smem = (size_t)(NT * SX + NT * SP + NT) * sizeof(float);
    cudaFuncSetAttribute(final_kernel, cudaFuncAttributeMaxDynamicSharedMemorySize, (int)smem);
    final_kernel<<<(N_NODES + NT - 1) / NT, 256, smem>>>(out, gate_b);
}

// round 11
// speedup vs baseline: 1.3412x; 1.0729x over previous
#include <cuda_runtime.h>
#include <cuda_fp16.h>
#include <cuda_bf16.h>
#include <math.h>

#define N_NODES 50000
#define NODE_DIM 64
#define DEPTH 2
#define FEAT 192           // 64*(DEPTH+1)
#define E_EDGES 1200000
#define R_REL 500
#define DEG 24

// ---------------- scratch (device globals: allocation-free) ----------------
__device__ float    g_attW[DEPTH * R_REL];      // per-relation attention logit per layer
__device__ __half   g_nrelh[R_REL * NODE_DIM];  // l2-normalized rel_emb (fp16)
__device__ __half   g_fh0[N_NODES * NODE_DIM];  // tanh(features) fp16 (layer-0 gather src)
__device__ __half   g_fh1[N_NODES * NODE_DIM];  // layer-0 output fp16 (layer-1 gather src)
// packed tf32 fragment-pair tables: pair (k0+t, k0+t+4) per uint2
__device__ unsigned g_npT2[2 * (FEAT / 8) * 64 * 4];     // normalized proxy^T
__device__ unsigned g_prx2[2 * 8 * FEAT * 4];            // proxy [k][n] (k=64)
__device__ unsigned g_Wt2[2 * (FEAT / 8) * FEAT * 4];    // gate_w^T [k][c]

__device__ __forceinline__ unsigned f2tf(float x) {
    unsigned r;
    asm("cvt.rna.tf32.f32 %0, %1;" : "=r"(r) : "f"(x));
    return r;
}
__device__ __forceinline__ float tf2f(unsigned b) { return __uint_as_float(b); }
__device__ __forceinline__ int packslot(int k, int c, int ncols) {
    return (((k >> 3) * ncols + c) * 4 + (k & 3)) * 2 + ((k >> 2) & 1);
}
__device__ __forceinline__ unsigned h2bits(__half2 h) {
    union { __half2 h; unsigned u; } cvt;
    cvt.h = h;
    return cvt.u;
}
__device__ __forceinline__ float2 unpk(unsigned u) {
    union { unsigned u; __half2 h; } cvt;
    cvt.u = u;
    return __half22float2(cvt.h);
}
__device__ __forceinline__ unsigned pack2h(float a, float b) {
    return h2bits(__float22half2_rn(make_float2(a, b)));
}

// ---------------- prep: normalize rel table + proxy(->packed tf32) ---------
__global__ void prep_kernel(const float* __restrict__ rel_emb,
                            const float* __restrict__ attn_kernels,
                            const float* __restrict__ proxy) {
    int w = (blockIdx.x * blockDim.x + threadIdx.x) >> 5;
    int lane = threadIdx.x & 31;
    if (w < R_REL) {
        float2 v = ((const float2*)(rel_emb + w * NODE_DIM))[lane];
        float ss = v.x * v.x + v.y * v.y;
        #pragma unroll
        for (int o = 16; o; o >>= 1) ss += __shfl_xor_sync(0xffffffffu, ss, o);
        float inv = 1.0f / fmaxf(sqrtf(ss), 1e-12f);
        float2 nv = make_float2(v.x * inv, v.y * inv);
        ((__half2*)(g_nrelh + w * NODE_DIM))[lane] = __float22half2_rn(nv);
        float2 a0 = ((const float2*)attn_kernels)[lane];
        float2 a1 = ((const float2*)(attn_kernels + NODE_DIM))[lane];
        float d0 = nv.x * a0.x + nv.y * a0.y;
        float d1 = nv.x * a1.x + nv.y * a1.y;
        #pragma unroll
        for (int o = 16; o; o >>= 1) {
            d0 += __shfl_xor_sync(0xffffffffu, d0, o);
            d1 += __shfl_xor_sync(0xffffffffu, d1, o);
        }
        if (lane == 0) { g_attW[w] = d0; g_attW[R_REL + w] = d1; }
    } else if (w < R_REL + 64) {
        int j = w - R_REL;
        float v[6];
        float ss = 0.f;
        #pragma unroll
        for (int t = 0; t < 6; t++) {
            v[t] = proxy[j * FEAT + lane + 32 * t];
            ss += v[t] * v[t];
        }
        #pragma unroll
        for (int o = 16; o; o >>= 1) ss += __shfl_xor_sync(0xffffffffu, ss, o);
        float inv = 1.0f / fmaxf(sqrtf(ss), 1e-12f);
        #pragma unroll
        for (int t = 0; t < 6; t++) {
            int k = lane + 32 * t;
            g_npT2[packslot(k, j, 64)] = f2tf(v[t] * inv);
        }
    }
}

// ---------------- pack gate_w (transposed) + proxy into tf32 pair tables ----
__global__ void convtab_kernel(const float* __restrict__ gw,
                               const float* __restrict__ proxy) {
    int idx = blockIdx.x * blockDim.x + threadIdx.x;
    if (idx < FEAT * FEAT) {
        int k = idx / FEAT, c = idx - k * FEAT;
        g_Wt2[packslot(k, c, FEAT)] = f2tf(gw[c * FEAT + k]);
    } else if (idx < FEAT * FEAT + 64 * FEAT) {
        int j = idx - FEAT * FEAT;
        int k = j / FEAT, c = j - k * FEAT;
        g_prx2[packslot(k, c, FEAT)] = f2tf(proxy[k * FEAT + c]);
    }
}

// ---------------- outputs[:,0:64] = tanh(features); fp16 side copy ---------
__global__ void tanh_kernel(const float* __restrict__ features, float* __restrict__ out) {
    int idx = blockIdx.x * blockDim.x + threadIdx.x;
    if (idx >= N_NODES * 16) return;
    int i = idx >> 4;
    int j4 = (idx & 15) << 2;
    float4 v = *(const float4*)(features + i * NODE_DIM + j4);
    float4 tv = make_float4(tanhf(v.x), tanhf(v.y), tanhf(v.z), tanhf(v.w));
    *(float4*)(out + (long)i * FEAT + j4) = tv;
    *(uint2*)(g_fh0 + i * NODE_DIM + j4) =
        make_uint2(pack2h(tv.x, tv.y), pack2h(tv.z, tv.w));
}

// ---------------- graph attention layer: warp per node, fp16 gathers -------
__global__ void __launch_bounds__(256) layer_kernel(
        float* __restrict__ out,
        const __half* __restrict__ fin,      // compact [N x 64] fp16 features
        __half* __restrict__ fout,           // next-level fp16 buffer (may be null)
        const int* __restrict__ src,
        const int* __restrict__ rid,
        const float* __restrict__ rval,
        int l) {
    __shared__ int4 s_meta[8 * DEG];
    int wb = threadIdx.x >> 5;
    int w = (blockIdx.x * blockDim.x + threadIdx.x) >> 5;
    int lane = threadIdx.x & 31;
    if (w >= N_NODES) return;
    int base = w * DEG;

    float att = -INFINITY;
    int ms = 0, mr = 0;
    if (lane < DEG) {
        int e = base + lane;
        ms = __ldg(src + e);
        mr = __ldg(rid + e);
        float sgn = __ldg(rval + e) < 0.f ? -1.f : 1.f;
        att = sgn * g_attW[l * R_REL + mr];
    }
    float m = att;
    #pragma unroll
    for (int o = 16; o; o >>= 1) m = fmaxf(m, __shfl_xor_sync(0xffffffffu, m, o));
    float ex = (lane < DEG) ? __expf(att - m) : 0.f;
    float s = ex;
    #pragma unroll
    for (int o = 16; o; o >>= 1) s += __shfl_xor_sync(0xffffffffu, s, o);
    float wgt = ex / s;

    if (lane < DEG)
        s_meta[wb * DEG + lane] = make_int4(ms * NODE_DIM,
                                            mr * NODE_DIM,
                                            __float_as_int(wgt), 0);
    __syncwarp();

    int half = lane >> 4;
    int q4 = (lane & 15) << 2;           // dims [q4, q4+4)
    float4 acc = make_float4(0.f, 0.f, 0.f, 0.f);
    #pragma unroll 4
    for (int i = 0; i < 12; i++) {
        int4 md = s_meta[wb * DEG + 2 * i + half];
        uint2 fu = *(const uint2*)(fin + md.x + q4);
        uint2 ru = *(const uint2*)(g_nrelh + md.y + q4);
        float2 f01 = unpk(fu.x), f23 = unpk(fu.y);
        float2 r01 = unpk(ru.x), r23 = unpk(ru.y);
        float d = f01.x * r01.x + f01.y * r01.y + f23.x * r23.x + f23.y * r23.y;
        #pragma unroll
        for (int o = 8; o; o >>= 1) d += __shfl_xor_sync(0xffffffffu, d, o);
        float we = __int_as_float(md.z);
        float t2 = 2.f * d;
        acc.x += we * (f01.x - t2 * r01.x);
        acc.y += we * (f01.y - t2 * r01.y);
        acc.z += we * (f23.x - t2 * r23.x);
        acc.w += we * (f23.y - t2 * r23.y);
    }
    acc.x += __shfl_xor_sync(0xffffffffu, acc.x, 16);
    acc.y += __shfl_xor_sync(0xffffffffu, acc.y, 16);
    acc.z += __shfl_xor_sync(0xffffffffu, acc.z, 16);
    acc.w += __shfl_xor_sync(0xffffffffu, acc.w, 16);

    if (half == 0) {
        float4 tv = make_float4(tanhf(acc.x), tanhf(acc.y), tanhf(acc.z), tanhf(acc.w));
        float* dst = out + (long)w * FEAT + NODE_DIM * (l + 1);
        *(float4*)(dst + q4) = tv;
        if (fout)
            *(uint2*)(fout + w * NODE_DIM + q4) =
                make_uint2(pack2h(tv.x, tv.y), pack2h(tv.z, tv.w));
    }
}

// ---------------- tf32 mma helper -------------------------------------------
__device__ __forceinline__ void mma8(float* d, const unsigned* a, const unsigned* b) {
    asm volatile(
        "mma.sync.aligned.m16n8k8.row.col.f32.tf32.tf32.f32 "
        "{%0,%1,%2,%3}, {%4,%5,%6,%7}, {%8,%9}, {%0,%1,%2,%3};\n"
        : "+f"(d[0]), "+f"(d[1]), "+f"(d[2]), "+f"(d[3])
        : "r"(a[0]), "r"(a[1]), "r"(a[2]), "r"(a[3]), "r"(b[0]), "r"(b[1]));
}

// ---------------- fused final stage (tensor-core tf32, pipelined B) ---------
#define NT 48
#define MT 3               // m16 tiles per block
#define SX 196
#define SP 68
__global__ void __launch_bounds__(256, 4) final_kernel(
        float* __restrict__ out,
        const float* __restrict__ gate_b) {
    extern __shared__ float smem[];
    float* s_x   = smem;                    // NT*196  (o tf32, later pf tf32)
    float* s_p   = s_x + NT * SX;           // NT*68
    float* s_inv = s_p + NT * SP;           // NT

    int tid = threadIdx.x;
    int w = tid >> 5, lane = tid & 31;
    int g = lane >> 2, t = lane & 3;
    int n0 = blockIdx.x * NT;
    int rows = N_NODES - n0; if (rows > NT) rows = NT;

    for (int i = tid; i < NT * 48; i += 256) {
        int r = i / 48, c4 = (i - r * 48) * 4;
        float4 v = (r < rows) ? *(const float4*)(out + (long)(n0 + r) * FEAT + c4)
                              : make_float4(0.f, 0.f, 0.f, 0.f);
        s_x[r * SX + c4]     = tf2f(f2tf(v.x));
        s_x[r * SX + c4 + 1] = tf2f(f2tf(v.y));
        s_x[r * SX + c4 + 2] = tf2f(f2tf(v.z));
        s_x[r * SX + c4 + 3] = tf2f(f2tf(v.w));
    }
    __syncthreads();

    for (int r = w * 6; r < w * 6 + 6; r++) {
        float ss = 0.f;
        #pragma unroll
        for (int tt = 0; tt < 6; tt++) {
            float v = s_x[r * SX + lane + 32 * tt];
            ss += v * v;
        }
        #pragma unroll
        for (int o = 16; o; o >>= 1) ss += __shfl_xor_sync(0xffffffffu, ss, o);
        if (lane == 0) s_inv[r] = 1.0f / fmaxf(sqrtf(ss), 1e-12f);
    }
    __syncthreads();

    // ---- GEMM1: logits[NT x 64] = o @ nproxy^T, depth-2 B prefetch ----
    {
        float d1[MT][4];
        #pragma unroll
        for (int mi = 0; mi < MT; mi++)
            #pragma unroll
            for (int q = 0; q < 4; q++) d1[mi][q] = 0.f;
        const uint2* B = (const uint2*)g_npT2;
        int bi = (8 * w + g) * 4 + t;
        uint2 bc = __ldg(B + bi);
        uint2 bn = __ldg(B + 256 + bi);
        #pragma unroll 2
        for (int kk = 0; kk < 24; kk++) {
            uint2 bf = make_uint2(0u, 0u);
            if (kk + 2 < 24) bf = __ldg(B + (kk + 2) * 256 + bi);
            unsigned bb[2] = {bc.x, bc.y};
            int k0 = kk * 8;
            #pragma unroll
            for (int mi = 0; mi < MT; mi++) {
                int r0 = 16 * mi + g;
                unsigned a[4];
                a[0] = __float_as_uint(s_x[r0 * SX + k0 + t]);
                a[1] = __float_as_uint(s_x[(r0 + 8) * SX + k0 + t]);
                a[2] = __float_as_uint(s_x[r0 * SX + k0 + t + 4]);
                a[3] = __float_as_uint(s_x[(r0 + 8) * SX + k0 + t + 4]);
                mma8(d1[mi], a, bb);
            }
            bc = bn; bn = bf;
        }
        #pragma unroll
        for (int mi = 0; mi < MT; mi++) {
            int r0 = 16 * mi + g;
            int c = 8 * w + 2 * t;
            float i0 = s_inv[r0], i1 = s_inv[r0 + 8];
            s_p[r0 * SP + c]       = d1[mi][0] * i0;
            s_p[r0 * SP + c + 1]   = d1[mi][1] * i0;
            s_p[(r0 + 8) * SP + c]     = d1[mi][2] * i1;
            s_p[(r0 + 8) * SP + c + 1] = d1[mi][3] * i1;
        }
    }
    __syncthreads();

    for (int r = w * 6; r < w * 6 + 6; r++) {
        float v0 = s_p[r * SP + lane];
        float v1 = s_p[r * SP + 32 + lane];
        float mx = fmaxf(v0, v1);
        #pragma unroll
        for (int o = 16; o; o >>= 1) mx = fmaxf(mx, __shfl_xor_sync(0xffffffffu, mx, o));
        float e0 = __expf(v0 - mx), e1 = __expf(v1 - mx);
        float sm = e0 + e1;
        #pragma unroll
        for (int o = 16; o; o >>= 1) sm += __shfl_xor_sync(0xffffffffu, sm, o);
        float invs = 1.0f / sm;
        s_p[r * SP + lane]      = tf2f(f2tf(e0 * invs));
        s_p[r * SP + 32 + lane] = tf2f(f2tf(e1 * invs));
    }
    __syncthreads();

    // ---- GEMM2: pf = o - P @ proxy (in-place), depth-1 B prefetch ----
    {
        float d2[3][MT][4];
        #pragma unroll
        for (int ni = 0; ni < 3; ni++)
            #pragma unroll
            for (int mi = 0; mi < MT; mi++)
                #pragma unroll
                for (int q = 0; q < 4; q++) d2[ni][mi][q] = 0.f;
        const uint2* B = (const uint2*)g_prx2;
        int bi = (24 * w + g) * 4 + t;
        uint2 bc[3], bn[3];
        #pragma unroll
        for (int ni = 0; ni < 3; ni++) bc[ni] = __ldg(B + bi + 32 * ni);
        for (int kk = 0; kk < 8; kk++) {
            if (kk + 1 < 8) {
                #pragma unroll
                for (int ni = 0; ni < 3; ni++)
                    bn[ni] = __ldg(B + (kk + 1) * 768 + bi + 32 * ni);
            }
            int k0 = kk * 8;
            unsigned a[MT][4];
            #pragma unroll
            for (int mi = 0; mi < MT; mi++) {
                int r0 = 16 * mi + g;
                a[mi][0] = __float_as_uint(s_p[r0 * SP + k0 + t]);
                a[mi][1] = __float_as_uint(s_p[(r0 + 8) * SP + k0 + t]);
                a[mi][2] = __float_as_uint(s_p[r0 * SP + k0 + t + 4]);
                a[mi][3] = __float_as_uint(s_p[(r0 + 8) * SP + k0 + t + 4]);
            }
            #pragma unroll
            for (int ni = 0; ni < 3; ni++) {
                unsigned bb[2] = {bc[ni].x, bc[ni].y};
                #pragma unroll
                for (int mi = 0; mi < MT; mi++) mma8(d2[ni][mi], a[mi], bb);
            }
            #pragma unroll
            for (int ni = 0; ni < 3; ni++) bc[ni] = bn[ni];
        }
        #pragma unroll
        for (int ni = 0; ni < 3; ni++) {
            int c = 24 * w + 8 * ni + 2 * t;
            #pragma unroll
            for (int mi = 0; mi < MT; mi++) {
                int r0 = 16 * mi + g;
                s_x[r0 * SX + c]       = tf2f(f2tf(s_x[r0 * SX + c]       - d2[ni][mi][0]));
                s_x[r0 * SX + c + 1]   = tf2f(f2tf(s_x[r0 * SX + c + 1]   - d2[ni][mi][1]));
                s_x[(r0 + 8) * SX + c]     = tf2f(f2tf(s_x[(r0 + 8) * SX + c]     - d2[ni][mi][2]));
                s_x[(r0 + 8) * SX + c + 1] = tf2f(f2tf(s_x[(r0 + 8) * SX + c + 1] - d2[ni][mi][3]));
            }
        }
    }
    __syncthreads();

    // ---- GEMM3: pf @ W^T + b -> sigmoid -> blend, depth-1 B prefetch ----
    {
        float d3[3][MT][4];
        #pragma unroll
        for (int ni = 0; ni < 3; ni++)
            #pragma unroll
            for (int mi = 0; mi < MT; mi++)
                #pragma unroll
                for (int q = 0; q < 4; q++) d3[ni][mi][q] = 0.f;
        const uint2* B = (const uint2*)g_Wt2;
        int bi = (24 * w + g) * 4 + t;
        uint2 bc[3], bn[3];
        #pragma unroll
        for (int ni = 0; ni < 3; ni++) bc[ni] = __ldg(B + bi + 32 * ni);
        #pragma unroll 2
        for (int kk = 0; kk < 24; kk++) {
            if (kk + 1 < 24) {
                #pragma unroll
                for (int ni = 0; ni < 3; ni++)
                    bn[ni] = __ldg(B + (kk + 1) * 768 + bi + 32 * ni);
            }
            int k0 = kk * 8;
            unsigned a[MT][4];
            #pragma unroll
            for (int mi = 0; mi < MT; mi++) {
                int r0 = 16 * mi + g;
                a[mi][0] = __float_as_uint(s_x[r0 * SX + k0 + t]);
                a[mi][1] = __float_as_uint(s_x[(r0 + 8) * SX + k0 + t]);
                a[mi][2] = __float_as_uint(s_x[r0 * SX + k0 + t + 4]);
                a[mi][3] = __float_as_uint(s_x[(r0 + 8) * SX + k0 + t + 4]);
            }
            #pragma unroll
            for (int ni = 0; ni < 3; ni++) {
                unsigned bb[2] = {bc[ni].x, bc[ni].y};
                #pragma unroll
                for (int mi = 0; mi < MT; mi++) mma8(d3[ni][mi], a[mi], bb);
            }
            #pragma unroll
            for (int ni = 0; ni < 3; ni++) bc[ni] = bn[ni];
        }
        #pragma unroll
        for (int ni = 0; ni < 3; ni++) {
            int c = 24 * w + 8 * ni + 2 * t;
            float b0 = __ldg(gate_b + c), b1 = __ldg(gate_b + c + 1);
            #pragma unroll
            for (int mi = 0; mi < MT; mi++) {
                int r0 = 16 * mi + g;
                #pragma unroll
                for (int half = 0; half < 2; half++) {
                    int r = r0 + 8 * half;
                    if (r >= rows) continue;
                    float p0 = d3[ni][mi][2 * half]     + b0;
                    float p1 = d3[ni][mi][2 * half + 1] + b1;
                    float g0 = 1.0f / (1.0f + __expf(-p0));
                    float g1 = 1.0f / (1.0f + __expf(-p1));
                    float2 o2 = *(const float2*)(out + (long)(n0 + r) * FEAT + c);
                    float pf0 = s_x[r * SX + c];
                    float pf1 = s_x[r * SX + c + 1];
                    float2 res = make_float2(g0 * o2.x + (1.0f - g0) * pf0,
                                             g1 * o2.y + (1.0f - g1) * pf1);
                    *(float2*)(out + (long)(n0 + r) * FEAT + c) = res;
                }
            }
        }
    }
}

extern "C" void kernel_launch(void* const* d_in, const int* in_sizes, int n_in,
                              void* d_out, int out_size) {
    const float* features     = (const float*)d_in[0];   // [N,64]
    const float* rel_emb      = (const float*)d_in[1];   // [R,64]
    const float* proxy        = (const float*)d_in[2];   // [64,192]
    const float* gate_w       = (const float*)d_in[3];   // [192,192]
    const float* gate_b       = (const float*)d_in[4];   // [192]
    const float* attn_kernels = (const float*)d_in[5];   // [2,64]
    const int*   adj          = (const int*)d_in[6];     // [2,E]
    const int*   r_index      = (const int*)d_in[7];     // [2,E]
    const float* r_val        = (const float*)d_in[8];   // [E]
    float* out = (float*)d_out;                          // [N,192]

    const int* src = adj + E_EDGES;
    const int* rid = r_index + E_EDGES;

    prep_kernel<<<(564 * 32 + 255) / 256, 256>>>(rel_emb, attn_kernels, proxy);
    convtab_kernel<<<(FEAT * FEAT + 64 * FEAT + 255) / 256, 256>>>(gate_w, proxy);

    tanh_kernel<<<(N_NODES * 16 + 255) / 256, 256>>>(features, out);

    __half* fh0; cudaGetSymbolAddress((void**)&fh0, g_fh0);
    __half* fh1; cudaGetSymbolAddress((void**)&fh1, g_fh1);

    int lgrid = (N_NODES * 32 + 255) / 256;
    layer_kernel<<<lgrid, 256>>>(out, fh0, fh1, src, rid, r_val, 0);
    layer_kernel<<<lgrid, 256>>>(out, fh1, (__half*)0, src, rid, r_val, 1);

    size_t smem = (size_t)(NT * SX + NT * SP + NT) * sizeof(float);
    cudaFuncSetAttribute(final_kernel, cudaFuncAttributeMaxDynamicSharedMemorySize, (int)smem);
    final_kernel<<<(N_NODES + NT - 1) / NT, 256, smem>>>(out, gate_b);
}

// round 12
// speedup vs baseline: 1.4438x; 1.0765x over previous
#include <cuda_runtime.h>
#include <cuda_fp16.h>
#include <cuda_bf16.h>
#include <math.h>

#define N_NODES 50000
#define NODE_DIM 64
#define DEPTH 2
#define FEAT 192           // 64*(DEPTH+1)
#define E_EDGES 1200000
#define R_REL 500
#define DEG 24

// ---------------- scratch (device globals: allocation-free) ----------------
__device__ float    g_attW[DEPTH * R_REL];      // per-relation attention logit per layer
__device__ __half   g_nrelh[R_REL * NODE_DIM];  // l2-normalized rel_emb (fp16)
__device__ __half   g_fh0[N_NODES * NODE_DIM];  // tanh(features) fp16 (layer-0 gather src)
__device__ __half   g_fh1[N_NODES * NODE_DIM];  // layer-0 output fp16 (layer-1 gather src)
// packed tf32 fragment-pair tables: pair (k0+t, k0+t+4) per uint2
__device__ unsigned g_npT2[2 * (FEAT / 8) * 64 * 4];     // normalized proxy^T
__device__ unsigned g_prx2[2 * 8 * FEAT * 4];            // proxy [k][n] (k=64)
__device__ unsigned g_Wt2[2 * (FEAT / 8) * FEAT * 4];    // gate_w^T [k][c]

__device__ __forceinline__ unsigned f2tf(float x) {
    unsigned r;
    asm("cvt.rna.tf32.f32 %0, %1;" : "=r"(r) : "f"(x));
    return r;
}
__device__ __forceinline__ float tf2f(unsigned b) { return __uint_as_float(b); }
__device__ __forceinline__ int packslot(int k, int c, int ncols) {
    return (((k >> 3) * ncols + c) * 4 + (k & 3)) * 2 + ((k >> 2) & 1);
}
__device__ __forceinline__ unsigned h2bits(__half2 h) {
    union { __half2 h; unsigned u; } cvt; cvt.h = h; return cvt.u;
}
__device__ __forceinline__ __half2 bits2h(unsigned u) {
    union { unsigned u; __half2 h; } cvt; cvt.u = u; return cvt.h;
}
__device__ __forceinline__ float2 unpk(unsigned u) {
    return __half22float2(bits2h(u));
}
__device__ __forceinline__ unsigned pack2h(float a, float b) {
    return h2bits(__float22half2_rn(make_float2(a, b)));
}

// ---------------- fused setup: tanh + table packing + rel normalize --------
// blocks [0, TB_TANH): tanh slab; [TB_TANH, TB_TANH+TB_TABS): tf32 tables;
// [TB_TANH+TB_TABS, ...): rel_emb normalize + attW + proxy normalize.
#define TB_TANH ((N_NODES * 16 + 255) / 256)                       // 3125
#define TB_TABS ((FEAT * FEAT + 64 * FEAT + 255) / 256)            // 192
#define TB_PREP ((564 * 32 + 255) / 256)                           // 71
__global__ void setup_kernel(const float* __restrict__ features,
                             float* __restrict__ out,
                             const float* __restrict__ rel_emb,
                             const float* __restrict__ attn_kernels,
                             const float* __restrict__ proxy,
                             const float* __restrict__ gw) {
    int b = blockIdx.x;
    if (b < TB_TANH) {
        int idx = b * blockDim.x + threadIdx.x;
        if (idx >= N_NODES * 16) return;
        int i = idx >> 4;
        int j4 = (idx & 15) << 2;
        float4 v = *(const float4*)(features + i * NODE_DIM + j4);
        float4 tv = make_float4(tanhf(v.x), tanhf(v.y), tanhf(v.z), tanhf(v.w));
        *(float4*)(out + (long)i * FEAT + j4) = tv;
        *(uint2*)(g_fh0 + i * NODE_DIM + j4) =
            make_uint2(pack2h(tv.x, tv.y), pack2h(tv.z, tv.w));
        return;
    }
    if (b < TB_TANH + TB_TABS) {
        int idx = (b - TB_TANH) * blockDim.x + threadIdx.x;
        if (idx < FEAT * FEAT) {
            int k = idx / FEAT, c = idx - k * FEAT;
            g_Wt2[packslot(k, c, FEAT)] = f2tf(gw[c * FEAT + k]);
        } else if (idx < FEAT * FEAT + 64 * FEAT) {
            int j = idx - FEAT * FEAT;
            int k = j / FEAT, c = j - k * FEAT;
            g_prx2[packslot(k, c, FEAT)] = f2tf(proxy[k * FEAT + c]);
        }
        return;
    }
    int w = ((b - TB_TANH - TB_TABS) * blockDim.x + threadIdx.x) >> 5;
    int lane = threadIdx.x & 31;
    if (w < R_REL) {
        float2 v = ((const float2*)(rel_emb + w * NODE_DIM))[lane];
        float ss = v.x * v.x + v.y * v.y;
        #pragma unroll
        for (int o = 16; o; o >>= 1) ss += __shfl_xor_sync(0xffffffffu, ss, o);
        float inv = 1.0f / fmaxf(sqrtf(ss), 1e-12f);
        float2 nv = make_float2(v.x * inv, v.y * inv);
        ((__half2*)(g_nrelh + w * NODE_DIM))[lane] = __float22half2_rn(nv);
        float2 a0 = ((const float2*)attn_kernels)[lane];
        float2 a1 = ((const float2*)(attn_kernels + NODE_DIM))[lane];
        float d0 = nv.x * a0.x + nv.y * a0.y;
        float d1 = nv.x * a1.x + nv.y * a1.y;
        #pragma unroll
        for (int o = 16; o; o >>= 1) {
            d0 += __shfl_xor_sync(0xffffffffu, d0, o);
            d1 += __shfl_xor_sync(0xffffffffu, d1, o);
        }
        if (lane == 0) { g_attW[w] = d0; g_attW[R_REL + w] = d1; }
    } else if (w < R_REL + 64) {
        int j = w - R_REL;
        float v[6];
        float ss = 0.f;
        #pragma unroll
        for (int t = 0; t < 6; t++) {
            v[t] = proxy[j * FEAT + lane + 32 * t];
            ss += v[t] * v[t];
        }
        #pragma unroll
        for (int o = 16; o; o >>= 1) ss += __shfl_xor_sync(0xffffffffu, ss, o);
        float inv = 1.0f / fmaxf(sqrtf(ss), 1e-12f);
        #pragma unroll
        for (int t = 0; t < 6; t++) {
            int k = lane + 32 * t;
            g_npT2[packslot(k, j, 64)] = f2tf(v[t] * inv);
        }
    }
}

// ---------------- graph attention layer: warp per node, half2 math ---------
__global__ void __launch_bounds__(256) layer_kernel(
        float* __restrict__ out,
        const __half* __restrict__ fin,      // compact [N x 64] fp16 features
        __half* __restrict__ fout,           // next-level fp16 buffer (may be null)
        const int* __restrict__ src,
        const int* __restrict__ rid,
        const float* __restrict__ rval,
        int l) {
    __shared__ int4 s_meta[8 * DEG];
    int wb = threadIdx.x >> 5;
    int w = (blockIdx.x * blockDim.x + threadIdx.x) >> 5;
    int lane = threadIdx.x & 31;
    if (w >= N_NODES) return;
    int base = w * DEG;

    float att = -INFINITY;
    int ms = 0, mr = 0;
    if (lane < DEG) {
        int e = base + lane;
        ms = __ldg(src + e);
        mr = __ldg(rid + e);
        float sgn = __ldg(rval + e) < 0.f ? -1.f : 1.f;
        att = sgn * g_attW[l * R_REL + mr];
    }
    float m = att;
    #pragma unroll
    for (int o = 16; o; o >>= 1) m = fmaxf(m, __shfl_xor_sync(0xffffffffu, m, o));
    float ex = (lane < DEG) ? __expf(att - m) : 0.f;
    float s = ex;
    #pragma unroll
    for (int o = 16; o; o >>= 1) s += __shfl_xor_sync(0xffffffffu, s, o);
    float wgt = ex / s;

    if (lane < DEG)
        s_meta[wb * DEG + lane] = make_int4(ms * NODE_DIM,
                                            mr * NODE_DIM,
                                            __float_as_int(wgt), 0);
    __syncwarp();

    int half = lane >> 4;
    int q4 = (lane & 15) << 2;           // dims [q4, q4+4)
    float4 acc = make_float4(0.f, 0.f, 0.f, 0.f);
    #pragma unroll 4
    for (int i = 0; i < 12; i++) {
        int4 md = s_meta[wb * DEG + 2 * i + half];
        uint2 fu = *(const uint2*)(fin + md.x + q4);
        uint2 ru = *(const uint2*)(g_nrelh + md.y + q4);
        __half2 f01 = bits2h(fu.x), f23 = bits2h(fu.y);
        __half2 r01 = bits2h(ru.x), r23 = bits2h(ru.y);
        // dot in half2 (inputs already fp16-quantized)
        __half2 dh = __hfma2(f23, r23, __hmul2(f01, r01));
        float d = __low2float(dh) + __high2float(dh);
        #pragma unroll
        for (int o = 8; o; o >>= 1) d += __shfl_xor_sync(0xffffffffu, d, o);
        // v = f - 2d*r in half2, accumulate in fp32
        __half2 nt2 = __float2half2_rn(-2.f * d);
        float2 v01 = __half22float2(__hfma2(nt2, r01, f01));
        float2 v23 = __half22float2(__hfma2(nt2, r23, f23));
        float we = __int_as_float(md.z);
        acc.x += we * v01.x;
        acc.y += we * v01.y;
        acc.z += we * v23.x;
        acc.w += we * v23.y;
    }
    acc.x += __shfl_xor_sync(0xffffffffu, acc.x, 16);
    acc.y += __shfl_xor_sync(0xffffffffu, acc.y, 16);
    acc.z += __shfl_xor_sync(0xffffffffu, acc.z, 16);
    acc.w += __shfl_xor_sync(0xffffffffu, acc.w, 16);

    if (half == 0) {
        float4 tv = make_float4(tanhf(acc.x), tanhf(acc.y), tanhf(acc.z), tanhf(acc.w));
        float* dst = out + (long)w * FEAT + NODE_DIM * (l + 1);
        *(float4*)(dst + q4) = tv;
        if (fout)
            *(uint2*)(fout + w * NODE_DIM + q4) =
                make_uint2(pack2h(tv.x, tv.y), pack2h(tv.z, tv.w));
    }
}

// ---------------- tf32 mma helper -------------------------------------------
__device__ __forceinline__ void mma8(float* d, const unsigned* a, const unsigned* b) {
    asm volatile(
        "mma.sync.aligned.m16n8k8.row.col.f32.tf32.tf32.f32 "
        "{%0,%1,%2,%3}, {%4,%5,%6,%7}, {%8,%9}, {%0,%1,%2,%3};\n"
        : "+f"(d[0]), "+f"(d[1]), "+f"(d[2]), "+f"(d[3])
        : "r"(a[0]), "r"(a[1]), "r"(a[2]), "r"(a[3]), "r"(b[0]), "r"(b[1]));
}

// ---------------- fused final stage (tensor-core tf32, pipelined B) ---------
#define NT 48
#define MT 3               // m16 tiles per block
#define SX 196
#define SP 68
__global__ void __launch_bounds__(256, 4) final_kernel(
        float* __restrict__ out,
        const float* __restrict__ gate_b) {
    extern __shared__ float smem[];
    float* s_x   = smem;                    // NT*196  (o tf32, later pf tf32)
    float* s_p   = s_x + NT * SX;           // NT*68
    float* s_inv = s_p + NT * SP;           // NT

    int tid = threadIdx.x;
    int w = tid >> 5, lane = tid & 31;
    int g = lane >> 2, t = lane & 3;
    int n0 = blockIdx.x * NT;
    int rows = N_NODES - n0; if (rows > NT) rows = NT;

    for (int i = tid; i < NT * 48; i += 256) {
        int r = i / 48, c4 = (i - r * 48) * 4;
        float4 v = (r < rows) ? *(const float4*)(out + (long)(n0 + r) * FEAT + c4)
                              : make_float4(0.f, 0.f, 0.f, 0.f);
        s_x[r * SX + c4]     = tf2f(f2tf(v.x));
        s_x[r * SX + c4 + 1] = tf2f(f2tf(v.y));
        s_x[r * SX + c4 + 2] = tf2f(f2tf(v.z));
        s_x[r * SX + c4 + 3] = tf2f(f2tf(v.w));
    }
    __syncthreads();

    for (int r = w * 6; r < w * 6 + 6; r++) {
        float ss = 0.f;
        #pragma unroll
        for (int tt = 0; tt < 6; tt++) {
            float v = s_x[r * SX + lane + 32 * tt];
            ss += v * v;
        }
        #pragma unroll
        for (int o = 16; o; o >>= 1) ss += __shfl_xor_sync(0xffffffffu, ss, o);
        if (lane == 0) s_inv[r] = 1.0f / fmaxf(sqrtf(ss), 1e-12f);
    }
    __syncthreads();

    // ---- GEMM1: logits[NT x 64] = o @ nproxy^T, depth-2 B prefetch ----
    {
        float d1[MT][4];
        #pragma unroll
        for (int mi = 0; mi < MT; mi++)
            #pragma unroll
            for (int q = 0; q < 4; q++) d1[mi][q] = 0.f;
        const uint2* B = (const uint2*)g_npT2;
        int bi = (8 * w + g) * 4 + t;
        uint2 bc = __ldg(B + bi);
        uint2 bn = __ldg(B + 256 + bi);
        #pragma unroll 2
        for (int kk = 0; kk < 24; kk++) {
            uint2 bf = make_uint2(0u, 0u);
            if (kk + 2 < 24) bf = __ldg(B + (kk + 2) * 256 + bi);
            unsigned bb[2] = {bc.x, bc.y};
            int k0 = kk * 8;
            #pragma unroll
            for (int mi = 0; mi < MT; mi++) {
                int r0 = 16 * mi + g;
                unsigned a[4];
                a[0] = __float_as_uint(s_x[r0 * SX + k0 + t]);
                a[1] = __float_as_uint(s_x[(r0 + 8) * SX + k0 + t]);
                a[2] = __float_as_uint(s_x[r0 * SX + k0 + t + 4]);
                a[3] = __float_as_uint(s_x[(r0 + 8) * SX + k0 + t + 4]);
                mma8(d1[mi], a, bb);
            }
            bc = bn; bn = bf;
        }
        #pragma unroll
        for (int mi = 0; mi < MT; mi++) {
            int r0 = 16 * mi + g;
            int c = 8 * w + 2 * t;
            float i0 = s_inv[r0], i1 = s_inv[r0 + 8];
            s_p[r0 * SP + c]       = d1[mi][0] * i0;
            s_p[r0 * SP + c + 1]   = d1[mi][1] * i0;
            s_p[(r0 + 8) * SP + c]     = d1[mi][2] * i1;
            s_p[(r0 + 8) * SP + c + 1] = d1[mi][3] * i1;
        }
    }
    __syncthreads();

    for (int r = w * 6; r < w * 6 + 6; r++) {
        float v0 = s_p[r * SP + lane];
        float v1 = s_p[r * SP + 32 + lane];
        float mx = fmaxf(v0, v1);
        #pragma unroll
        for (int o = 16; o; o >>= 1) mx = fmaxf(mx, __shfl_xor_sync(0xffffffffu, mx, o));
        float e0 = __expf(v0 - mx), e1 = __expf(v1 - mx);
        float sm = e0 + e1;
        #pragma unroll
        for (int o = 16; o; o >>= 1) sm += __shfl_xor_sync(0xffffffffu, sm, o);
        float invs = 1.0f / sm;
        s_p[r * SP + lane]      = tf2f(f2tf(e0 * invs));
        s_p[r * SP + 32 + lane] = tf2f(f2tf(e1 * invs));
    }
    __syncthreads();

    // ---- GEMM2: pf = o - P @ proxy (in-place), depth-1 B prefetch ----
    {
        float d2[3][MT][4];
        #pragma unroll
        for (int ni = 0; ni < 3; ni++)
            #pragma unroll
            for (int mi = 0; mi < MT; mi++)
                #pragma unroll
                for (int q = 0; q < 4; q++) d2[ni][mi][q] = 0.f;
        const uint2* B = (const uint2*)g_prx2;
        int bi = (24 * w + g) * 4 + t;
        uint2 bc[3], bn[3];
        #pragma unroll
        for (int ni = 0; ni < 3; ni++) bc[ni] = __ldg(B + bi + 32 * ni);
        for (int kk = 0; kk < 8; kk++) {
            if (kk + 1 < 8) {
                #pragma unroll
                for (int ni = 0; ni < 3; ni++)
                    bn[ni] = __ldg(B + (kk + 1) * 768 + bi + 32 * ni);
            }
            int k0 = kk * 8;
            unsigned a[MT][4];
            #pragma unroll
            for (int mi = 0; mi < MT; mi++) {
                int r0 = 16 * mi + g;
                a[mi][0] = __float_as_uint(s_p[r0 * SP + k0 + t]);
                a[mi][1] = __float_as_uint(s_p[(r0 + 8) * SP + k0 + t]);
                a[mi][2] = __float_as_uint(s_p[r0 * SP + k0 + t + 4]);
                a[mi][3] = __float_as_uint(s_p[(r0 + 8) * SP + k0 + t + 4]);
            }
            #pragma unroll
            for (int ni = 0; ni < 3; ni++) {
                unsigned bb[2] = {bc[ni].x, bc[ni].y};
                #pragma unroll
                for (int mi = 0; mi < MT; mi++) mma8(d2[ni][mi], a[mi], bb);
            }
            #pragma unroll
            for (int ni = 0; ni < 3; ni++) bc[ni] = bn[ni];
        }
        #pragma unroll
        for (int ni = 0; ni < 3; ni++) {
            int c = 24 * w + 8 * ni + 2 * t;
            #pragma unroll
            for (int mi = 0; mi < MT; mi++) {
                int r0 = 16 * mi + g;
                s_x[r0 * SX + c]       = tf2f(f2tf(s_x[r0 * SX + c]       - d2[ni][mi][0]));
                s_x[r0 * SX + c + 1]   = tf2f(f2tf(s_x[r0 * SX + c + 1]   - d2[ni][mi][1]));
                s_x[(r0 + 8) * SX + c]     = tf2f(f2tf(s_x[(r0 + 8) * SX + c]     - d2[ni][mi][2]));
                s_x[(r0 + 8) * SX + c + 1] = tf2f(f2tf(s_x[(r0 + 8) * SX + c + 1] - d2[ni][mi][3]));
            }
        }
    }
    __syncthreads();

    // ---- GEMM3: pf @ W^T + b -> sigmoid -> blend, depth-1 B prefetch ----
    {
        float d3[3][MT][4];
        #pragma unroll
        for (int ni = 0; ni < 3; ni++)
            #pragma unroll
            for (int mi = 0; mi < MT; mi++)
                #pragma unroll
                for (int q = 0; q < 4; q++) d3[ni][mi][q] = 0.f;
        const uint2* B = (const uint2*)g_Wt2;
        int bi = (24 * w + g) * 4 + t;
        uint2 bc[3], bn[3];
        #pragma unroll
        for (int ni = 0; ni < 3; ni++) bc[ni] = __ldg(B + bi + 32 * ni);
        #pragma unroll 2
        for (int kk = 0; kk < 24; kk++) {
            if (kk + 1 < 24) {
                #pragma unroll
                for (int ni = 0; ni < 3; ni++)
                    bn[ni] = __ldg(B + (kk + 1) * 768 + bi + 32 * ni);
            }
            int k0 = kk * 8;
            unsigned a[MT][4];
            #pragma unroll
            for (int mi = 0; mi < MT; mi++) {
                int r0 = 16 * mi + g;
                a[mi][0] = __float_as_uint(s_x[r0 * SX + k0 + t]);
                a[mi][1] = __float_as_uint(s_x[(r0 + 8) * SX + k0 + t]);
                a[mi][2] = __float_as_uint(s_x[r0 * SX + k0 + t + 4]);
                a[mi][3] = __float_as_uint(s_x[(r0 + 8) * SX + k0 + t + 4]);
            }
            #pragma unroll
            for (int ni = 0; ni < 3; ni++) {
                unsigned bb[2] = {bc[ni].x, bc[ni].y};
                #pragma unroll
                for (int mi = 0; mi < MT; mi++) mma8(d3[ni][mi], a[mi], bb);
            }
            #pragma unroll
            for (int ni = 0; ni < 3; ni++) bc[ni] = bn[ni];
        }
        #pragma unroll
        for (int ni = 0; ni < 3; ni++) {
            int c = 24 * w + 8 * ni + 2 * t;
            float b0 = __ldg(gate_b + c), b1 = __ldg(gate_b + c + 1);
            #pragma unroll
            for (int mi = 0; mi < MT; mi++) {
                int r0 = 16 * mi + g;
                #pragma unroll
                for (int half = 0; half < 2; half++) {
                    int r = r0 + 8 * half;
                    if (r >= rows) continue;
                    float p0 = d3[ni][mi][2 * half]     + b0;
                    float p1 = d3[ni][mi][2 * half + 1] + b1;
                    float g0 = 1.0f / (1.0f + __expf(-p0));
                    float g1 = 1.0f / (1.0f + __expf(-p1));
                    float2 o2 = *(const float2*)(out + (long)(n0 + r) * FEAT + c);
                    float pf0 = s_x[r * SX + c];
                    float pf1 = s_x[r * SX + c + 1];
                    float2 res = make_float2(g0 * o2.x + (1.0f - g0) * pf0,
                                             g1 * o2.y + (1.0f - g1) * pf1);
                    *(float2*)(out + (long)(n0 + r) * FEAT + c) = res;
                }
            }
        }
    }
}

extern "C" void kernel_launch(void* const* d_in, const int* in_sizes, int n_in,
                              void* d_out, int out_size) {
    const float* features     = (const float*)d_in[0];   // [N,64]
    const float* rel_emb      = (const float*)d_in[1];   // [R,64]
    const float* proxy        = (const float*)d_in[2];   // [64,192]
    const float* gate_w       = (const float*)d_in[3];   // [192,192]
    const float* gate_b       = (const float*)d_in[4];   // [192]
    const float* attn_kernels = (const float*)d_in[5];   // [2,64]
    const int*   adj          = (const int*)d_in[6];     // [2,E]
    const int*   r_index      = (const int*)d_in[7];     // [2,E]
    const float* r_val        = (const float*)d_in[8];   // [E]
    float* out = (float*)d_out;                          // [N,192]

    const int* src = adj + E_EDGES;
    const int* rid = r_index + E_EDGES;

    setup_kernel<<<TB_TANH + TB_TABS + TB_PREP, 256>>>(
        features, out, rel_emb, attn_kernels, proxy, gate_w);

    __half* fh0; cudaGetSymbolAddress((void**)&fh0, g_fh0);
    __half* fh1; cudaGetSymbolAddress((void**)&fh1, g_fh1);

    int lgrid = (N_NODES * 32 + 255) / 256;
    layer_kernel<<<lgrid, 256>>>(out, fh0, fh1, src, rid, r_val, 0);
    layer_kernel<<<lgrid, 256>>>(out, fh1, (__half*)0, src, rid, r_val, 1);

    size_t smem = (size_t)(NT * SX + NT * SP + NT) * sizeof(float);
    cudaFuncSetAttribute(final_kernel, cudaFuncAttributeMaxDynamicSharedMemorySize, (int)smem);
    final_kernel<<<(N_NODES + NT - 1) / NT, 256, smem>>>(out, gate_b);
}

// round 14
// speedup vs baseline: 1.7949x; 1.2432x over previous
#include <cuda_runtime.h>
#include <cuda_fp16.h>
#include <cuda_bf16.h>
#include <math.h>

#define N_NODES 50000
#define NODE_DIM 64
#define DEPTH 2
#define FEAT 192           // 64*(DEPTH+1)
#define E_EDGES 1200000
#define R_REL 500
#define DEG 24

// ---------------- scratch (device globals: allocation-free) ----------------
__device__ float    g_attW[DEPTH * R_REL];      // per-relation attention logit per layer
__device__ __half   g_nrelh[R_REL * NODE_DIM];  // l2-normalized rel_emb (fp16)
__device__ __half   g_fh0[N_NODES * NODE_DIM];  // tanh(features) fp16
__device__ __half   g_fh1[N_NODES * NODE_DIM];  // layer-0 output fp16
// fp16 MMA B-fragment tables: uint2 per (k16-step, col, t): (b0,b1) halves
__device__ uint2 g_npTH[12 * 64 * 4];           // normalized proxy^T  (k=192, n=64)
__device__ uint2 g_prxH[4 * 192 * 4];           // proxy [k][n]        (k=64,  n=192)
__device__ uint2 g_WtH[12 * 192 * 4];           // gate_w^T [k][c]     (k=192, n=192)

__device__ __forceinline__ unsigned h2bits(__half2 h) {
    union { __half2 h; unsigned u; } c; c.h = h; return c.u;
}
__device__ __forceinline__ __half2 bits2h(unsigned u) {
    union { unsigned u; __half2 h; } c; c.u = u; return c.h;
}
__device__ __forceinline__ float2 unpk(unsigned u) { return __half22float2(bits2h(u)); }
__device__ __forceinline__ unsigned pack2h(float a, float b) {
    return h2bits(__float22half2_rn(make_float2(a, b)));
}
// half index inside the uint2-pair B table for element (k, c)
__device__ __forceinline__ int packslotH(int k, int c, int ncols) {
    return ((((k >> 4) * ncols + c) * 4 + ((k >> 1) & 3)) * 4)
         + (((k >> 3) & 1) * 2) + (k & 1);
}

// ---------------- fused setup: tanh + fp16 table packing + rel normalize ---
#define TB_TANH ((N_NODES * 16 + 255) / 256)
#define TB_TABS ((FEAT * FEAT + 64 * FEAT + 255) / 256)
#define TB_PREP ((564 * 32 + 255) / 256)
__global__ void setup_kernel(const float* __restrict__ features,
                             float* __restrict__ out,
                             const float* __restrict__ rel_emb,
                             const float* __restrict__ attn_kernels,
                             const float* __restrict__ proxy,
                             const float* __restrict__ gw) {
    int b = blockIdx.x;
    if (b < TB_TANH) {
        int idx = b * blockDim.x + threadIdx.x;
        if (idx >= N_NODES * 16) return;
        int i = idx >> 4;
        int j4 = (idx & 15) << 2;
        float4 v = *(const float4*)(features + i * NODE_DIM + j4);
        float4 tv = make_float4(tanhf(v.x), tanhf(v.y), tanhf(v.z), tanhf(v.w));
        *(float4*)(out + (long)i * FEAT + j4) = tv;
        *(uint2*)(g_fh0 + i * NODE_DIM + j4) =
            make_uint2(pack2h(tv.x, tv.y), pack2h(tv.z, tv.w));
        return;
    }
    if (b < TB_TANH + TB_TABS) {
        int idx = (b - TB_TANH) * blockDim.x + threadIdx.x;
        if (idx < FEAT * FEAT) {
            int k = idx / FEAT, c = idx - k * FEAT;
            ((__half*)g_WtH)[packslotH(k, c, FEAT)] = __float2half_rn(gw[c * FEAT + k]);
        } else if (idx < FEAT * FEAT + 64 * FEAT) {
            int j = idx - FEAT * FEAT;
            int k = j / FEAT, c = j - k * FEAT;
            ((__half*)g_prxH)[packslotH(k, c, FEAT)] = __float2half_rn(proxy[k * FEAT + c]);
        }
        return;
    }
    int w = ((b - TB_TANH - TB_TABS) * blockDim.x + threadIdx.x) >> 5;
    int lane = threadIdx.x & 31;
    if (w < R_REL) {
        float2 v = ((const float2*)(rel_emb + w * NODE_DIM))[lane];
        float ss = v.x * v.x + v.y * v.y;
        #pragma unroll
        for (int o = 16; o; o >>= 1) ss += __shfl_xor_sync(0xffffffffu, ss, o);
        float inv = 1.0f / fmaxf(sqrtf(ss), 1e-12f);
        float2 nv = make_float2(v.x * inv, v.y * inv);
        ((__half2*)(g_nrelh + w * NODE_DIM))[lane] = __float22half2_rn(nv);
        float2 a0 = ((const float2*)attn_kernels)[lane];
        float2 a1 = ((const float2*)(attn_kernels + NODE_DIM))[lane];
        float d0 = nv.x * a0.x + nv.y * a0.y;
        float d1 = nv.x * a1.x + nv.y * a1.y;
        #pragma unroll
        for (int o = 16; o; o >>= 1) {
            d0 += __shfl_xor_sync(0xffffffffu, d0, o);
            d1 += __shfl_xor_sync(0xffffffffu, d1, o);
        }
        if (lane == 0) { g_attW[w] = d0; g_attW[R_REL + w] = d1; }
    } else if (w < R_REL + 64) {
        int j = w - R_REL;
        float v[6];
        float ss = 0.f;
        #pragma unroll
        for (int t = 0; t < 6; t++) {
            v[t] = proxy[j * FEAT + lane + 32 * t];
            ss += v[t] * v[t];
        }
        #pragma unroll
        for (int o = 16; o; o >>= 1) ss += __shfl_xor_sync(0xffffffffu, ss, o);
        float inv = 1.0f / fmaxf(sqrtf(ss), 1e-12f);
        #pragma unroll
        for (int t = 0; t < 6; t++) {
            int k = lane + 32 * t;
            ((__half*)g_npTH)[packslotH(k, j, 64)] = __float2half_rn(v[t] * inv);
        }
    }
}

// ---------------- graph attention layer: warp per node, half2 math ---------
__global__ void __launch_bounds__(256) layer_kernel(
        float* __restrict__ out,
        const __half* __restrict__ fin,
        __half* __restrict__ fout,
        const int* __restrict__ src,
        const int* __restrict__ rid,
        const float* __restrict__ rval,
        int l) {
    __shared__ int4 s_meta[8 * DEG];
    int wb = threadIdx.x >> 5;
    int w = (blockIdx.x * blockDim.x + threadIdx.x) >> 5;
    int lane = threadIdx.x & 31;
    if (w >= N_NODES) return;
    int base = w * DEG;

    float att = -INFINITY;
    int ms = 0, mr = 0;
    if (lane < DEG) {
        int e = base + lane;
        ms = __ldg(src + e);
        mr = __ldg(rid + e);
        float sgn = __ldg(rval + e) < 0.f ? -1.f : 1.f;
        att = sgn * g_attW[l * R_REL + mr];
    }
    float m = att;
    #pragma unroll
    for (int o = 16; o; o >>= 1) m = fmaxf(m, __shfl_xor_sync(0xffffffffu, m, o));
    float ex = (lane < DEG) ? __expf(att - m) : 0.f;
    float s = ex;
    #pragma unroll
    for (int o = 16; o; o >>= 1) s += __shfl_xor_sync(0xffffffffu, s, o);
    float wgt = ex / s;

    if (lane < DEG)
        s_meta[wb * DEG + lane] = make_int4(ms * NODE_DIM,
                                            mr * NODE_DIM,
                                            __float_as_int(wgt), 0);
    __syncwarp();

    int half = lane >> 4;
    int q4 = (lane & 15) << 2;
    float4 acc = make_float4(0.f, 0.f, 0.f, 0.f);
    #pragma unroll 4
    for (int i = 0; i < 12; i++) {
        int4 md = s_meta[wb * DEG + 2 * i + half];
        uint2 fu = *(const uint2*)(fin + md.x + q4);
        uint2 ru = *(const uint2*)(g_nrelh + md.y + q4);
        __half2 f01 = bits2h(fu.x), f23 = bits2h(fu.y);
        __half2 r01 = bits2h(ru.x), r23 = bits2h(ru.y);
        __half2 dh = __hfma2(f23, r23, __hmul2(f01, r01));
        float d = __low2float(dh) + __high2float(dh);
        #pragma unroll
        for (int o = 8; o; o >>= 1) d += __shfl_xor_sync(0xffffffffu, d, o);
        __half2 nt2 = __float2half2_rn(-2.f * d);
        float2 v01 = __half22float2(__hfma2(nt2, r01, f01));
        float2 v23 = __half22float2(__hfma2(nt2, r23, f23));
        float we = __int_as_float(md.z);
        acc.x += we * v01.x;
        acc.y += we * v01.y;
        acc.z += we * v23.x;
        acc.w += we * v23.y;
    }
    acc.x += __shfl_xor_sync(0xffffffffu, acc.x, 16);
    acc.y += __shfl_xor_sync(0xffffffffu, acc.y, 16);
    acc.z += __shfl_xor_sync(0xffffffffu, acc.z, 16);
    acc.w += __shfl_xor_sync(0xffffffffu, acc.w, 16);

    if (half == 0) {
        float4 tv = make_float4(tanhf(acc.x), tanhf(acc.y), tanhf(acc.z), tanhf(acc.w));
        float* dst = out + (long)w * FEAT + NODE_DIM * (l + 1);
        *(float4*)(dst + q4) = tv;
        if (fout)
            *(uint2*)(fout + w * NODE_DIM + q4) =
                make_uint2(pack2h(tv.x, tv.y), pack2h(tv.z, tv.w));
    }
}

// ---------------- fp16 m16n8k16 mma helper ----------------------------------
__device__ __forceinline__ void mma16(float* d, const unsigned* a, const unsigned* b) {
    asm volatile(
        "mma.sync.aligned.m16n8k16.row.col.f32.f16.f16.f32 "
        "{%0,%1,%2,%3}, {%4,%5,%6,%7}, {%8,%9}, {%0,%1,%2,%3};\n"
        : "+f"(d[0]), "+f"(d[1]), "+f"(d[2]), "+f"(d[3])
        : "r"(a[0]), "r"(a[1]), "r"(a[2]), "r"(a[3]), "r"(b[0]), "r"(b[1]));
}

// ---------------- fused final stage (fp16 tensor-core) ----------------------
// s_x / s_p hold half2-packed rows; 26.3 KB smem -> tables L1-resident.
#define NT 48
#define MT 3
#define SXH 100            // uint stride: 96 half2-pairs + pad
#define SPH 36             // uint stride: 32 half2-pairs + pad
__global__ void __launch_bounds__(256, 4) final_kernel(
        float* __restrict__ out,
        const float* __restrict__ gate_b) {
    extern __shared__ unsigned smem_u[];
    unsigned* s_x  = smem_u;                 // NT*SXH (o fp16 pairs, later pf)
    unsigned* s_p  = s_x + NT * SXH;         // NT*SPH (logits/probs fp16 pairs)
    float*    s_inv = (float*)(s_p + NT * SPH);  // NT

    int tid = threadIdx.x;
    int w = tid >> 5, lane = tid & 31;
    int g = lane >> 2, t = lane & 3;
    int n0 = blockIdx.x * NT;
    int rows = N_NODES - n0; if (rows > NT) rows = NT;

    // ---- load o tile -> half2 pairs ----
    for (int i = tid; i < NT * 48; i += 256) {
        int r = i / 48, q = i - r * 48;          // q indexes float4s
        float4 v = (r < rows) ? *(const float4*)(out + (long)(n0 + r) * FEAT + q * 4)
                              : make_float4(0.f, 0.f, 0.f, 0.f);
        s_x[r * SXH + 2 * q]     = pack2h(v.x, v.y);
        s_x[r * SXH + 2 * q + 1] = pack2h(v.z, v.w);
    }
    __syncthreads();

    // ---- row inverse norms (6 rows per warp) ----
    for (int r = w * 6; r < w * 6 + 6; r++) {
        float ss = 0.f;
        #pragma unroll
        for (int tt = 0; tt < 3; tt++) {
            float2 v = unpk(s_x[r * SXH + lane + 32 * tt]);
            ss += v.x * v.x + v.y * v.y;
        }
        #pragma unroll
        for (int o = 16; o; o >>= 1) ss += __shfl_xor_sync(0xffffffffu, ss, o);
        if (lane == 0) s_inv[r] = 1.0f / fmaxf(sqrtf(ss), 1e-12f);
    }
    __syncthreads();

    // ---- GEMM1: logits[NT x 64] = o @ nproxy^T (12 k16-steps) ----
    {
        float d1[MT][4];
        #pragma unroll
        for (int mi = 0; mi < MT; mi++)
            #pragma unroll
            for (int q = 0; q < 4; q++) d1[mi][q] = 0.f;
        int bi = (8 * w + g) * 4 + t;            // + kk*256
        uint2 bc = __ldg(g_npTH + bi);
        for (int kk = 0; kk < 12; kk++) {
            uint2 bn = make_uint2(0u, 0u);
            if (kk + 1 < 12) bn = __ldg(g_npTH + (kk + 1) * 256 + bi);
            #pragma unroll
            for (int mi = 0; mi < MT; mi++) {
                int r0 = 16 * mi + g;
                unsigned a[4];
                a[0] = s_x[r0 * SXH + 8 * kk + t];
                a[1] = s_x[(r0 + 8) * SXH + 8 * kk + t];
                a[2] = s_x[r0 * SXH + 8 * kk + t + 4];
                a[3] = s_x[(r0 + 8) * SXH + 8 * kk + t + 4];
                mma16(d1[mi], a, (const unsigned*)&bc);
            }
            bc = bn;
        }
        int pc = 4 * w + t;                      // logits pair (cols 8w+2t, +1)
        #pragma unroll
        for (int mi = 0; mi < MT; mi++) {
            int r0 = 16 * mi + g;
            float i0 = s_inv[r0], i1 = s_inv[r0 + 8];
            s_p[r0 * SPH + pc]       = pack2h(d1[mi][0] * i0, d1[mi][1] * i0);
            s_p[(r0 + 8) * SPH + pc] = pack2h(d1[mi][2] * i1, d1[mi][3] * i1);
        }
    }
    __syncthreads();

    // ---- softmax over 64 per row (6 rows per warp, 2 vals/lane) ----
    for (int r = w * 6; r < w * 6 + 6; r++) {
        float2 v = unpk(s_p[r * SPH + lane]);
        float mx = fmaxf(v.x, v.y);
        #pragma unroll
        for (int o = 16; o; o >>= 1) mx = fmaxf(mx, __shfl_xor_sync(0xffffffffu, mx, o));
        float e0 = __expf(v.x - mx), e1 = __expf(v.y - mx);
        float sm = e0 + e1;
        #pragma unroll
        for (int o = 16; o; o >>= 1) sm += __shfl_xor_sync(0xffffffffu, sm, o);
        float invs = 1.0f / sm;
        s_p[r * SPH + lane] = pack2h(e0 * invs, e1 * invs);
    }
    __syncthreads();

    // ---- GEMM2: pf = o - P @ proxy (4 k16-steps), in-place on s_x ----
    {
        float d2[3][MT][4];
        #pragma unroll
        for (int ni = 0; ni < 3; ni++)
            #pragma unroll
            for (int mi = 0; mi < MT; mi++)
                #pragma unroll
                for (int q = 0; q < 4; q++) d2[ni][mi][q] = 0.f;
        int bi = (24 * w + g) * 4 + t;           // + ni*32 + kk*768
        uint2 bc[3], bn[3];
        #pragma unroll
        for (int ni = 0; ni < 3; ni++) bc[ni] = __ldg(g_prxH + bi + 32 * ni);
        for (int kk = 0; kk < 4; kk++) {
            if (kk + 1 < 4) {
                #pragma unroll
                for (int ni = 0; ni < 3; ni++)
                    bn[ni] = __ldg(g_prxH + (kk + 1) * 768 + bi + 32 * ni);
            }
            unsigned a[MT][4];
            #pragma unroll
            for (int mi = 0; mi < MT; mi++) {
                int r0 = 16 * mi + g;
                a[mi][0] = s_p[r0 * SPH + 8 * kk + t];
                a[mi][1] = s_p[(r0 + 8) * SPH + 8 * kk + t];
                a[mi][2] = s_p[r0 * SPH + 8 * kk + t + 4];
                a[mi][3] = s_p[(r0 + 8) * SPH + 8 * kk + t + 4];
            }
            #pragma unroll
            for (int ni = 0; ni < 3; ni++)
                #pragma unroll
                for (int mi = 0; mi < MT; mi++)
                    mma16(d2[ni][mi], a[mi], (const unsigned*)&bc[ni]);
            #pragma unroll
            for (int ni = 0; ni < 3; ni++) bc[ni] = bn[ni];
        }
        #pragma unroll
        for (int ni = 0; ni < 3; ni++) {
            int pc = 12 * w + 4 * ni + t;        // pf pair (cols 24w+8ni+2t, +1)
            #pragma unroll
            for (int mi = 0; mi < MT; mi++) {
                int r0 = 16 * mi + g;
                float2 o0 = unpk(s_x[r0 * SXH + pc]);
                float2 o1 = unpk(s_x[(r0 + 8) * SXH + pc]);
                s_x[r0 * SXH + pc]       = pack2h(o0.x - d2[ni][mi][0], o0.y - d2[ni][mi][1]);
                s_x[(r0 + 8) * SXH + pc] = pack2h(o1.x - d2[ni][mi][2], o1.y - d2[ni][mi][3]);
            }
        }
    }
    __syncthreads();

    // ---- GEMM3: pf @ W^T + b -> sigmoid -> blend (12 k16-steps) ----
    {
        float d3[3][MT][4];
        #pragma unroll
        for (int ni = 0; ni < 3; ni++)
            #pragma unroll
            for (int mi = 0; mi < MT; mi++)
                #pragma unroll
                for (int q = 0; q < 4; q++) d3[ni][mi][q] = 0.f;
        int bi = (24 * w + g) * 4 + t;           // + ni*32 + kk*768
        uint2 bc[3], bn[3];
        #pragma unroll
        for (int ni = 0; ni < 3; ni++) bc[ni] = __ldg(g_WtH + bi + 32 * ni);
        #pragma unroll 2
        for (int kk = 0; kk < 12; kk++) {
            if (kk + 1 < 12) {
                #pragma unroll
                for (int ni = 0; ni < 3; ni++)
                    bn[ni] = __ldg(g_WtH + (kk + 1) * 768 + bi + 32 * ni);
            }
            unsigned a[MT][4];
            #pragma unroll
            for (int mi = 0; mi < MT; mi++) {
                int r0 = 16 * mi + g;
                a[mi][0] = s_x[r0 * SXH + 8 * kk + t];
                a[mi][1] = s_x[(r0 + 8) * SXH + 8 * kk + t];
                a[mi][2] = s_x[r0 * SXH + 8 * kk + t + 4];
                a[mi][3] = s_x[(r0 + 8) * SXH + 8 * kk + t + 4];
            }
            #pragma unroll
            for (int ni = 0; ni < 3; ni++)
                #pragma unroll
                for (int mi = 0; mi < MT; mi++)
                    mma16(d3[ni][mi], a[mi], (const unsigned*)&bc[ni]);
            #pragma unroll
            for (int ni = 0; ni < 3; ni++) bc[ni] = bn[ni];
        }
        #pragma unroll
        for (int ni = 0; ni < 3; ni++) {
            int c = 24 * w + 8 * ni + 2 * t;
            int pc = c >> 1;                     // = 12w + 4ni + t
            float b0 = __ldg(gate_b + c), b1 = __ldg(gate_b + c + 1);
            #pragma unroll
            for (int mi = 0; mi < MT; mi++) {
                int r0 = 16 * mi + g;
                #pragma unroll
                for (int half = 0; half < 2; half++) {
                    int r = r0 + 8 * half;
                    if (r >= rows) continue;
                    float p0 = d3[ni][mi][2 * half]     + b0;
                    float p1 = d3[ni][mi][2 * half + 1] + b1;
                    float g0 = 1.0f / (1.0f + __expf(-p0));
                    float g1 = 1.0f / (1.0f + __expf(-p1));
                    float2 o2 = *(const float2*)(out + (long)(n0 + r) * FEAT + c);
                    float2 pf = unpk(s_x[r * SXH + pc]);
                    float2 res = make_float2(g0 * o2.x + (1.0f - g0) * pf.x,
                                             g1 * o2.y + (1.0f - g1) * pf.y);
                    *(float2*)(out + (long)(n0 + r) * FEAT + c) = res;
                }
            }
        }
    }
}

extern "C" void kernel_launch(void* const* d_in, const int* in_sizes, int n_in,
                              void* d_out, int out_size) {
    const float* features     = (const float*)d_in[0];   // [N,64]
    const float* rel_emb      = (const float*)d_in[1];   // [R,64]
    const float* proxy        = (const float*)d_in[2];   // [64,192]
    const float* gate_w       = (const float*)d_in[3];   // [192,192]
    const float* gate_b       = (const float*)d_in[4];   // [192]
    const float* attn_kernels = (const float*)d_in[5];   // [2,64]
    const int*   adj          = (const int*)d_in[6];     // [2,E]
    const int*   r_index      = (const int*)d_in[7];     // [2,E]
    const float* r_val        = (const float*)d_in[8];   // [E]
    float* out = (float*)d_out;                          // [N,192]

    const int* src = adj + E_EDGES;
    const int* rid = r_index + E_EDGES;

    setup_kernel<<<TB_TANH + TB_TABS + TB_PREP, 256>>>(
        features, out, rel_emb, attn_kernels, proxy, gate_w);

    __half* fh0; cudaGetSymbolAddress((void**)&fh0, g_fh0);
    __half* fh1; cudaGetSymbolAddress((void**)&fh1, g_fh1);

    int lgrid = (N_NODES * 32 + 255) / 256;
    layer_kernel<<<lgrid, 256>>>(out, fh0, fh1, src, rid, r_val, 0);
    layer_kernel<<<lgrid, 256>>>(out, fh1, (__half*)0, src, rid, r_val, 1);

    size_t smem = (size_t)(NT * SXH + NT * SPH) * sizeof(unsigned) + NT * sizeof(float);
    cudaFuncSetAttribute(final_kernel, cudaFuncAttributeMaxDynamicSharedMemorySize, (int)smem);
    final_kernel<<<(N_NODES + NT - 1) / NT, 256, smem>>>(out, gate_b);
}